// round 2
// baseline (speedup 1.0000x reference)
#include <cuda_runtime.h>
#include <cstddef>

// Problem constants
#define BB     128
#define TT     512
#define HALF_T 256
#define DD     512
#define NCLS   7
#define MROWS  (BB * HALF_T)   // 32768 rows fed to FFN / head

// ---------------------------------------------------------------------------
// Device scratch (static __device__ arrays: allocation-free per harness rules)
// ---------------------------------------------------------------------------
__device__ float g_gx[MROWS * 1536];   // input projections, rows = b*256 + t
__device__ float g_e [MROWS * DD];     // emotions (first half only) == P
__device__ float g_x1[MROWS * DD];
__device__ float g_x2[MROWS * DD];
__device__ float g_x3[MROWS * DD];
__device__ float g_h [2][BB * DD];     // double-buffered GRU hidden state
__device__ float g_Wc[NCLS * DD];      // W_out @ W_half  [7,512]
__device__ float g_s [NCLS];           // rowsum(W_comb)
__device__ float g_bc[NCLS];           // W_out @ b_half + b_out
__device__ unsigned g_ctr;             // grid barrier counter (monotonic)

// ---------------------------------------------------------------------------
// Init: zero h[0] and the barrier counter (must reset every graph replay)
// ---------------------------------------------------------------------------
__global__ void k_init() {
    int idx = blockIdx.x * 256 + threadIdx.x;
    if (idx < BB * DD) g_h[0][idx] = 0.0f;
    if (idx == 0) g_ctr = 0u;
}

// ---------------------------------------------------------------------------
// prep1: W_comb[n,k] = sum_j W_out[n,j] * W_half[j,k]   (7*512 threads)
// ---------------------------------------------------------------------------
__global__ void k_prep1(const float* __restrict__ W_half,
                        const float* __restrict__ W_out) {
    int idx = blockIdx.x * 256 + threadIdx.x;
    if (idx >= NCLS * DD) return;
    int n = idx / DD, k = idx % DD;
    float s = 0.0f;
    for (int j = 0; j < 256; j++)
        s += W_out[n * 256 + j] * W_half[j * DD + k];
    g_Wc[idx] = s;
}

// ---------------------------------------------------------------------------
// prep2: g_s[n] = rowsum(W_comb[n]);  g_bc[n] = W_out[n]·b_half + b_out[n]
// ---------------------------------------------------------------------------
__global__ void k_prep2(const float* __restrict__ W_out,
                        const float* __restrict__ b_half,
                        const float* __restrict__ b_out) {
    int tid = threadIdx.x;
    int w = tid >> 5, l = tid & 31;
    if (w < NCLS) {
        float s = 0.0f;
        #pragma unroll
        for (int i = 0; i < 16; i++) s += g_Wc[w * DD + i * 32 + l];
        #pragma unroll
        for (int off = 16; off > 0; off >>= 1)
            s += __shfl_xor_sync(0xffffffffu, s, off);
        if (l == 0) g_s[w] = s;
    }
    if (tid < NCLS) {
        float b = b_out[tid];
        for (int j = 0; j < 256; j++)
            b += W_out[tid * 256 + j] * b_half[j];
        g_bc[tid] = b;
    }
}

// ---------------------------------------------------------------------------
// SGEMM: C[m,n] = act( sum_k A[m,k]*B[n,k] + bias[n] )
//   A row-major [M,K]; B row-major [N,K] (i.e. computes A @ B^T).
//   permA==1: A row m maps to x0 row ( (m/256)*512 + (m%256) ), K must be 512.
//   BM=BN=128, BK=8, 256 threads, 8x8 per-thread tile, float4, reg prefetch.
//   M,N multiples of 128; K multiple of 8 (true for all call sites).
// ---------------------------------------------------------------------------
__global__ void __launch_bounds__(256)
k_sgemm(const float* __restrict__ A, const float* __restrict__ B,
        const float* __restrict__ bias, float* __restrict__ C,
        int M, int N, int K, int act, int permA) {
    __shared__ float As[8][128];
    __shared__ float Bs[8][128];
    int tid = threadIdx.x;
    int m0 = blockIdx.y << 7, n0 = blockIdx.x << 7;
    int lrow = tid >> 1, lcol = (tid & 1) << 2;

    int arow = m0 + lrow;
    size_t aoff;
    if (permA) aoff = (size_t)((arow >> 8) * 512 + (arow & 255)) * 512;
    else       aoff = (size_t)arow * K;
    const float* Ap = A + aoff + lcol;
    const float* Bp = B + (size_t)(n0 + lrow) * K + lcol;

    int tx = tid & 15, ty = tid >> 4;
    float acc[8][8];
    #pragma unroll
    for (int i = 0; i < 8; i++)
        #pragma unroll
        for (int j = 0; j < 8; j++) acc[i][j] = 0.0f;

    float4 av = *(const float4*)(Ap);
    float4 bv = *(const float4*)(Bp);

    for (int k0 = 0; k0 < K; k0 += 8) {
        float4 avn = av, bvn = bv;
        if (k0 + 8 < K) {
            avn = *(const float4*)(Ap + k0 + 8);
            bvn = *(const float4*)(Bp + k0 + 8);
        }
        As[lcol + 0][lrow] = av.x; As[lcol + 1][lrow] = av.y;
        As[lcol + 2][lrow] = av.z; As[lcol + 3][lrow] = av.w;
        Bs[lcol + 0][lrow] = bv.x; Bs[lcol + 1][lrow] = bv.y;
        Bs[lcol + 2][lrow] = bv.z; Bs[lcol + 3][lrow] = bv.w;
        __syncthreads();
        #pragma unroll
        for (int kk = 0; kk < 8; kk++) {
            float a[8], b[8];
            *(float4*)(a)     = *(const float4*)&As[kk][(ty << 3)];
            *(float4*)(a + 4) = *(const float4*)&As[kk][(ty << 3) + 4];
            *(float4*)(b)     = *(const float4*)&Bs[kk][(tx << 3)];
            *(float4*)(b + 4) = *(const float4*)&Bs[kk][(tx << 3) + 4];
            #pragma unroll
            for (int i = 0; i < 8; i++)
                #pragma unroll
                for (int j = 0; j < 8; j++)
                    acc[i][j] += a[i] * b[j];
        }
        __syncthreads();
        av = avn; bv = bvn;
    }

    #pragma unroll
    for (int i = 0; i < 8; i++) {
        size_t crow = (size_t)(m0 + (ty << 3) + i) * N + n0 + (tx << 3);
        #pragma unroll
        for (int j4 = 0; j4 < 8; j4 += 4) {
            float4 bvv = *(const float4*)&bias[n0 + (tx << 3) + j4];
            float4 v;
            v.x = acc[i][j4 + 0] + bvv.x;
            v.y = acc[i][j4 + 1] + bvv.y;
            v.z = acc[i][j4 + 2] + bvv.z;
            v.w = acc[i][j4 + 3] + bvv.w;
            if (act) { v.x = tanhf(v.x); v.y = tanhf(v.y);
                       v.z = tanhf(v.z); v.w = tanhf(v.w); }
            *(float4*)&C[crow + j4] = v;
        }
    }
}

// ---------------------------------------------------------------------------
// Persistent GRU scan, 256 steps.
//   128 blocks x 256 threads. Block `blk` owns hidden columns d0..d0+3
//   (W_hh rows {d, 512+d, 1024+d} = 12 rows, k-major in SMEM, loaded ONCE).
//   Per step: stage full h (128x512) in SMEM in 4 k-tiles, compute
//   gh[128 x 12] (k-split over 2 thread groups), apply GRU gate math,
//   write h_new + emotions, grid barrier (monotonic counter).
//   Grid <= SM count => all CTAs resident => no deadlock.
// ---------------------------------------------------------------------------
#define SCAN_SMEM_FLOATS (6144 + 16896 + 3072 + 16)
#define SCAN_SMEM_BYTES  (SCAN_SMEM_FLOATS * 4)

__global__ void __launch_bounds__(256, 1)
k_scan(const float* __restrict__ Whh, const float* __restrict__ bhh) {
    extern __shared__ float sm[];
    float* ws  = sm;                    // [512][12]  k-major W slice
    float* hs  = sm + 6144;             // [128][132] h tile, transposed [k][bi]
    float* ghs = sm + 6144 + 16896;     // [2][128][12] partial gh
    float* bsh = ghs + 3072;            // [12] b_hh slice

    int tid = threadIdx.x;
    int blk = blockIdx.x;
    int d0  = blk << 2;

    for (int idx = tid; idx < 6144; idx += 256) {
        int k = idx / 12, j = idx % 12;
        int gate = j >> 2, c = j & 3;
        ws[idx] = Whh[(size_t)(gate * 512 + d0 + c) * 512 + k];
    }
    if (tid < 12) bsh[tid] = bhh[(tid >> 2) * 512 + d0 + (tid & 3)];
    __syncthreads();

    int kg  = tid >> 7;       // k-split group (0/1)
    int ct  = tid & 127;
    int jt  = ct & 3;         // j-tile: j = 3*jt + jj
    int bit = ct >> 2;        // bi-tile: bi = 4*bit + m
    int p = 0;

    for (int t = 0; t < HALF_T; t++) {
        float acc[12];
        #pragma unroll
        for (int i = 0; i < 12; i++) acc[i] = 0.0f;
        const float* hsrc = g_h[p];

        for (int kt = 0; kt < 4; kt++) {
            int kofs = kt << 7;
            for (int idx = tid; idx < 16384; idx += 256) {
                int bi = idx >> 7, k = idx & 127;
                hs[k * 132 + bi] = __ldcg(hsrc + bi * 512 + kofs + k);
            }
            __syncthreads();
            int kbase = kg << 6;
            const float* wtile = ws + (size_t)kofs * 12;   // global-k weight tile
            #pragma unroll 8
            for (int kk = 0; kk < 64; kk++) {
                int k = kbase + kk;
                float4 hv = *(const float4*)(hs + k * 132 + (bit << 2));
                const float* wp = wtile + k * 12 + jt * 3;
                float w0 = wp[0], w1 = wp[1], w2 = wp[2];
                acc[0] += hv.x * w0; acc[1]  += hv.x * w1; acc[2]  += hv.x * w2;
                acc[3] += hv.y * w0; acc[4]  += hv.y * w1; acc[5]  += hv.y * w2;
                acc[6] += hv.z * w0; acc[7]  += hv.z * w1; acc[8]  += hv.z * w2;
                acc[9] += hv.w * w0; acc[10] += hv.w * w1; acc[11] += hv.w * w2;
            }
            __syncthreads();
        }
        {
            int bb = bit << 2;
            #pragma unroll
            for (int m = 0; m < 4; m++)
                #pragma unroll
                for (int jj = 0; jj < 3; jj++)
                    ghs[kg * 1536 + (bb + m) * 12 + jt * 3 + jj] = acc[m * 3 + jj];
        }
        __syncthreads();

        for (int o = tid; o < 512; o += 256) {
            int bi = o >> 2, c = o & 3;
            int d = d0 + c;
            int row = bi * HALF_T + t;
            float ghr = ghs[bi * 12 + c]     + ghs[1536 + bi * 12 + c]     + bsh[c];
            float ghz = ghs[bi * 12 + 4 + c] + ghs[1536 + bi * 12 + 4 + c] + bsh[4 + c];
            float ghn = ghs[bi * 12 + 8 + c] + ghs[1536 + bi * 12 + 8 + c] + bsh[8 + c];
            const float* gxr = g_gx + (size_t)row * 1536;
            float r = 1.0f / (1.0f + __expf(-(gxr[d]        + ghr)));
            float z = 1.0f / (1.0f + __expf(-(gxr[512 + d]  + ghz)));
            float n = tanhf(gxr[1024 + d] + r * ghn);
            float hold = __ldcg(hsrc + bi * 512 + d);
            float hn = (1.0f - z) * n + z * hold;
            g_h[p ^ 1][bi * 512 + d] = hn;
            g_e[(size_t)row * 512 + d] = hn;
        }

        // grid barrier: every thread fences its writes, then one thread signals
        __threadfence();
        __syncthreads();
        if (tid == 0) {
            unsigned target = (unsigned)(t + 1) * (unsigned)gridDim.x;
            atomicAdd(&g_ctr, 1u);
            volatile unsigned* vc = &g_ctr;
            while (*vc < target) { }
        }
        __syncthreads();
        p ^= 1;
    }
}

// ---------------------------------------------------------------------------
// Fused head: out[m] = logsoftmax(f[m]) @ W_comb^T + b_comb
//           = f[m]@W_comb^T - (max+lse)*rowsum(W_comb) + b_comb
//   warp per row, f kept in registers (16 floats/lane).
// ---------------------------------------------------------------------------
__global__ void __launch_bounds__(256)
k_final(const float* __restrict__ X, float* __restrict__ out) {
    __shared__ float Wc[NCLS * DD];
    __shared__ float ss[NCLS], bc[NCLS];
    int tid = threadIdx.x;
    for (int idx = tid; idx < NCLS * DD; idx += 256) Wc[idx] = g_Wc[idx];
    if (tid < NCLS) { ss[tid] = g_s[tid]; bc[tid] = g_bc[tid]; }
    __syncthreads();

    int w = tid >> 5, l = tid & 31;
    int m = (blockIdx.x << 3) + w;
    const float* xr = X + (size_t)m * DD;

    float f[16];
    #pragma unroll
    for (int i = 0; i < 16; i++) f[i] = xr[i * 32 + l];

    float mx = f[0];
    #pragma unroll
    for (int i = 1; i < 16; i++) mx = fmaxf(mx, f[i]);
    #pragma unroll
    for (int off = 16; off > 0; off >>= 1)
        mx = fmaxf(mx, __shfl_xor_sync(0xffffffffu, mx, off));

    float se = 0.0f;
    #pragma unroll
    for (int i = 0; i < 16; i++) se += __expf(f[i] - mx);
    #pragma unroll
    for (int off = 16; off > 0; off >>= 1)
        se += __shfl_xor_sync(0xffffffffu, se, off);
    float c = mx + __logf(se);

    #pragma unroll
    for (int n = 0; n < NCLS; n++) {
        float dot = 0.0f;
        const float* wr = Wc + n * DD;
        #pragma unroll
        for (int i = 0; i < 16; i++) dot += f[i] * wr[i * 32 + l];
        #pragma unroll
        for (int off = 16; off > 0; off >>= 1)
            dot += __shfl_xor_sync(0xffffffffu, dot, off);
        if (l == 0) out[m * NCLS + n] = dot - c * ss[n] + bc[n];
    }
}

// ---------------------------------------------------------------------------
// kernel_launch
// ---------------------------------------------------------------------------
extern "C" void kernel_launch(void* const* d_in, const int* in_sizes, int n_in,
                              void* d_out, int out_size) {
    (void)in_sizes; (void)out_size;
    if (n_in < 17) return;
    const float* x0     = (const float*)d_in[0];
    const float* W_ih   = (const float*)d_in[3];
    const float* W_hh   = (const float*)d_in[4];
    const float* b_ih   = (const float*)d_in[5];
    const float* b_hh   = (const float*)d_in[6];
    const float* W1     = (const float*)d_in[7];
    const float* bb1    = (const float*)d_in[8];
    const float* W2     = (const float*)d_in[9];
    const float* bb2    = (const float*)d_in[10];
    const float* W3     = (const float*)d_in[11];
    const float* bb3    = (const float*)d_in[12];
    const float* W_half = (const float*)d_in[13];
    const float* b_half = (const float*)d_in[14];
    const float* W_out  = (const float*)d_in[15];
    const float* b_out  = (const float*)d_in[16];
    float* out = (float*)d_out;

    float *gx, *e, *x1, *x2, *x3;
    cudaGetSymbolAddress((void**)&gx, g_gx);
    cudaGetSymbolAddress((void**)&e,  g_e);
    cudaGetSymbolAddress((void**)&x1, g_x1);
    cudaGetSymbolAddress((void**)&x2, g_x2);
    cudaGetSymbolAddress((void**)&x3, g_x3);

    cudaFuncSetAttribute(k_scan, cudaFuncAttributeMaxDynamicSharedMemorySize,
                         SCAN_SMEM_BYTES);

    k_init<<<256, 256>>>();
    k_prep1<<<14, 256>>>(W_half, W_out);
    k_prep2<<<1, 256>>>(W_out, b_half, b_out);

    // gx = x0(first half, permuted rows) @ W_ih^T + b_ih   [32768 x 1536]
    k_sgemm<<<dim3(12, 256), 256>>>(x0, W_ih, b_ih, gx, MROWS, 1536, 512, 0, 1);

    // GRU scan (256 steps), writes g_e
    k_scan<<<128, 256, SCAN_SMEM_BYTES>>>(W_hh, b_hh);

    // FFN
    k_sgemm<<<dim3(4, 256), 256>>>(e,  W1, bb1, x1, MROWS, 512, 512, 1, 0);
    k_sgemm<<<dim3(4, 256), 256>>>(x1, W2, bb2, x2, MROWS, 512, 512, 1, 0);
    k_sgemm<<<dim3(4, 256), 256>>>(x2, W3, bb3, x3, MROWS, 512, 512, 0, 0);

    // fused log_softmax + combined classifier head
    k_final<<<MROWS / 8, 256>>>(x3, out);
}

// round 3
// speedup vs baseline: 1.9549x; 1.9549x over previous
#include <cuda_runtime.h>
#include <cstddef>

// Problem constants
#define BB     128
#define TT     512
#define HALF_T 256
#define DD     512
#define NCLS   7
#define MROWS  (BB * HALF_T)   // 32768 rows fed to FFN / head

typedef unsigned long long ull;

// ---------------------------------------------------------------------------
// Packed fp32 helpers (fma.rn.f32x2 — SASS FFMA2, 2 FMA per issue slot)
// ---------------------------------------------------------------------------
__device__ __forceinline__ ull pk2(float x, float y) {
    ull r;
    asm("mov.b64 %0, {%1, %2};" : "=l"(r)
        : "r"(__float_as_uint(x)), "r"(__float_as_uint(y)));
    return r;
}
__device__ __forceinline__ void fma2(ull& d, ull a, ull b) {
    asm("fma.rn.f32x2 %0, %1, %2, %0;" : "+l"(d) : "l"(a), "l"(b));
}
__device__ __forceinline__ float2 upk2(ull v) {
    unsigned lo, hi;
    asm("mov.b64 {%0, %1}, %2;" : "=r"(lo), "=r"(hi) : "l"(v));
    float2 r; r.x = __uint_as_float(lo); r.y = __uint_as_float(hi);
    return r;
}

// ---------------------------------------------------------------------------
// Device scratch
// ---------------------------------------------------------------------------
__device__ float g_gx[MROWS * 1536];   // input projections, rows = b*256 + t
__device__ float g_e [MROWS * DD];     // emotions (first half only) == P
__device__ float g_x1[MROWS * DD];
__device__ float g_x2[MROWS * DD];
__device__ float g_x3[MROWS * DD];
__device__ float g_h [2][BB * DD];     // double-buffered GRU hidden state
__device__ float g_Wc[NCLS * DD];      // W_out @ W_half  [7,512]
__device__ float g_s [NCLS];           // rowsum(W_comb)
__device__ float g_bc[NCLS];           // W_out @ b_half + b_out
__device__ unsigned g_ctr4[4];         // per-batch-group barrier counters

// ---------------------------------------------------------------------------
// Init: zero h[0] and barrier counters (must reset every graph replay)
// ---------------------------------------------------------------------------
__global__ void k_init() {
    int idx = blockIdx.x * 256 + threadIdx.x;
    if (idx < BB * DD) g_h[0][idx] = 0.0f;
    if (idx < 4) g_ctr4[idx] = 0u;
}

// ---------------------------------------------------------------------------
// prep1: W_comb[n,k] = sum_j W_out[n,j] * W_half[j,k]
// ---------------------------------------------------------------------------
__global__ void k_prep1(const float* __restrict__ W_half,
                        const float* __restrict__ W_out) {
    int idx = blockIdx.x * 256 + threadIdx.x;
    if (idx >= NCLS * DD) return;
    int n = idx / DD, k = idx % DD;
    float s = 0.0f;
    for (int j = 0; j < 256; j++)
        s += W_out[n * 256 + j] * W_half[j * DD + k];
    g_Wc[idx] = s;
}

// ---------------------------------------------------------------------------
// prep2: g_s[n] = rowsum(W_comb[n]);  g_bc[n] = W_out[n]·b_half + b_out[n]
// ---------------------------------------------------------------------------
__global__ void k_prep2(const float* __restrict__ W_out,
                        const float* __restrict__ b_half,
                        const float* __restrict__ b_out) {
    int tid = threadIdx.x;
    int w = tid >> 5, l = tid & 31;
    if (w < NCLS) {
        float s = 0.0f;
        #pragma unroll
        for (int i = 0; i < 16; i++) s += g_Wc[w * DD + i * 32 + l];
        #pragma unroll
        for (int off = 16; off > 0; off >>= 1)
            s += __shfl_xor_sync(0xffffffffu, s, off);
        if (l == 0) g_s[w] = s;
    }
    if (tid < NCLS) {
        float b = b_out[tid];
        for (int j = 0; j < 256; j++)
            b += W_out[tid * 256 + j] * b_half[j];
        g_bc[tid] = b;
    }
}

// ---------------------------------------------------------------------------
// SGEMM (f32x2 core): C[m,n] = act( sum_k A[m,k]*B[n,k] + bias[n] )
//   BM=BN=128, BK=8, 256 threads, 8x8 per-thread tile.
//   Inner product uses FFMA2: B pairs loaded as 64-bit from smem,
//   A broadcast-packed via MOV (alu pipe, overlaps fma pipe).
// ---------------------------------------------------------------------------
__global__ void __launch_bounds__(256)
k_sgemm(const float* __restrict__ A, const float* __restrict__ B,
        const float* __restrict__ bias, float* __restrict__ C,
        int M, int N, int K, int act, int permA) {
    __shared__ float As[8][128];
    __shared__ float Bs[8][128];
    int tid = threadIdx.x;
    int m0 = blockIdx.y << 7, n0 = blockIdx.x << 7;
    int lrow = tid >> 1, lcol = (tid & 1) << 2;

    int arow = m0 + lrow;
    size_t aoff;
    if (permA) aoff = (size_t)((arow >> 8) * 512 + (arow & 255)) * 512;
    else       aoff = (size_t)arow * K;
    const float* Ap = A + aoff + lcol;
    const float* Bp = B + (size_t)(n0 + lrow) * K + lcol;

    int tx = tid & 15, ty = tid >> 4;
    ull acc2[8][4];
    #pragma unroll
    for (int i = 0; i < 8; i++)
        #pragma unroll
        for (int j = 0; j < 4; j++) acc2[i][j] = 0ull;

    float4 av = *(const float4*)(Ap);
    float4 bv = *(const float4*)(Bp);

    for (int k0 = 0; k0 < K; k0 += 8) {
        float4 avn = av, bvn = bv;
        if (k0 + 8 < K) {
            avn = *(const float4*)(Ap + k0 + 8);
            bvn = *(const float4*)(Bp + k0 + 8);
        }
        As[lcol + 0][lrow] = av.x; As[lcol + 1][lrow] = av.y;
        As[lcol + 2][lrow] = av.z; As[lcol + 3][lrow] = av.w;
        Bs[lcol + 0][lrow] = bv.x; Bs[lcol + 1][lrow] = bv.y;
        Bs[lcol + 2][lrow] = bv.z; Bs[lcol + 3][lrow] = bv.w;
        __syncthreads();
        #pragma unroll
        for (int kk = 0; kk < 8; kk++) {
            float a[8];
            *(float4*)(a)     = *(const float4*)&As[kk][(ty << 3)];
            *(float4*)(a + 4) = *(const float4*)&As[kk][(ty << 3) + 4];
            ull bu[4];
            *(ulonglong2*)(bu)     = *(const ulonglong2*)&Bs[kk][(tx << 3)];
            *(ulonglong2*)(bu + 2) = *(const ulonglong2*)&Bs[kk][(tx << 3) + 4];
            #pragma unroll
            for (int i = 0; i < 8; i++) {
                ull ap = pk2(a[i], a[i]);
                #pragma unroll
                for (int j = 0; j < 4; j++)
                    fma2(acc2[i][j], ap, bu[j]);
            }
        }
        __syncthreads();
        av = avn; bv = bvn;
    }

    #pragma unroll
    for (int i = 0; i < 8; i++) {
        size_t crow = (size_t)(m0 + (ty << 3) + i) * N + n0 + (tx << 3);
        #pragma unroll
        for (int j2 = 0; j2 < 4; j2 += 2) {
            float4 bvv = *(const float4*)&bias[n0 + (tx << 3) + (j2 << 1)];
            float2 p0 = upk2(acc2[i][j2]);
            float2 p1 = upk2(acc2[i][j2 + 1]);
            float4 v;
            v.x = p0.x + bvv.x; v.y = p0.y + bvv.y;
            v.z = p1.x + bvv.z; v.w = p1.y + bvv.w;
            if (act) { v.x = tanhf(v.x); v.y = tanhf(v.y);
                       v.z = tanhf(v.z); v.w = tanhf(v.w); }
            *(float4*)&C[crow + (j2 << 1)] = v;
        }
    }
}

// ---------------------------------------------------------------------------
// Persistent GRU scan, 256 steps. 2-D tiling: 4 batch-groups x 32 d-groups.
//   CTA (bg,dg) owns batch rows [bg*32, bg*32+32) and hidden cols
//   [dg*16, dg*16+16)  -> 48 W_hh rows (96KB smem, loaded ONCE).
//   Per step: stage its h slice [32 x 512] transposed into smem, compute
//   gh[32 x 48] with FFMA2 (k-split over 2 halves), gate math, write
//   h_new + emotions, per-batch-group grid barrier (32 arrivals).
// ---------------------------------------------------------------------------
#define WS_F   (512 * 48)       // 24576 floats
#define HS_F   (512 * 36)       // 18432 floats (pad 36 => LDS.64-aligned)
#define GHS_F  (2 * 32 * 48)    // 3072
#define SCAN_SMEM_FLOATS (WS_F + HS_F + GHS_F + 64)
#define SCAN_SMEM_BYTES  (SCAN_SMEM_FLOATS * 4)

__global__ void __launch_bounds__(256, 1)
k_scan(const float* __restrict__ Whh, const float* __restrict__ bhh) {
    extern __shared__ float sm[];
    float* ws  = sm;                 // [512][48]  k-major, j = g*16+dc
    float* hs  = sm + WS_F;          // [512][36]  transposed h slice [k][bi]
    float* ghs = hs + HS_F;          // [2][32][48] partial gh
    float* bsh = ghs + GHS_F;        // [48]

    int tid = threadIdx.x;
    int blk = blockIdx.x;
    int bg  = blk >> 5;              // batch group 0..3
    int dg  = blk & 31;              // d group 0..31
    int d0  = dg << 4;
    int b0  = bg << 5;

    for (int idx = tid; idx < WS_F; idx += 256) {
        int k = idx / 48, j = idx - k * 48;
        int g = j >> 4, dc = j & 15;
        ws[idx] = Whh[(size_t)(g * 512 + d0 + dc) * 512 + k];
    }
    if (tid < 48) bsh[tid] = bhh[(tid >> 4) * 512 + d0 + (tid & 15)];
    __syncthreads();

    // compute-thread mapping
    int kg  = tid >> 7;              // k half (0/1)
    int ct  = tid & 127;
    int js  = ct & 15;               // j = js*3 + jj
    int biq = ((ct >> 4) & 7) << 2;  // bi quad base
    int kbeg = kg << 8;

    // epilogue mapping: outputs o = tid and tid+256
    int bi_a = tid >> 4;             // 0..15 ; second output bi_a+16
    int dc_a = tid & 15;
    int d_a  = d0 + dc_a;
    int p = 0;

    for (int t = 0; t < HALF_T; t++) {
        // prefetch gx gate values for this step's two outputs
        size_t rowA = (size_t)((b0 + bi_a) * 256 + t) * 1536;
        size_t rowB = (size_t)((b0 + bi_a + 16) * 256 + t) * 1536;
        float gxrA = __ldcg(g_gx + rowA + d_a);
        float gxzA = __ldcg(g_gx + rowA + 512 + d_a);
        float gxnA = __ldcg(g_gx + rowA + 1024 + d_a);
        float gxrB = __ldcg(g_gx + rowB + d_a);
        float gxzB = __ldcg(g_gx + rowB + 512 + d_a);
        float gxnB = __ldcg(g_gx + rowB + 1024 + d_a);

        const float* hsrc = g_h[p];

        // stage h slice [32][512] -> hs[k][bi]  (coalesced gmem reads)
        for (int idx = tid; idx < 4096; idx += 256) {
            int bi = idx >> 7;
            int k4 = (idx & 127) << 2;
            float4 v = __ldcg((const float4*)(hsrc + (size_t)(b0 + bi) * 512 + k4));
            hs[(k4 + 0) * 36 + bi] = v.x;
            hs[(k4 + 1) * 36 + bi] = v.y;
            hs[(k4 + 2) * 36 + bi] = v.z;
            hs[(k4 + 3) * 36 + bi] = v.w;
        }
        __syncthreads();

        ull a0 = 0, a1 = 0, a2 = 0, a3 = 0, a4 = 0, a5 = 0;
        {
            const float* hp = hs + kbeg * 36 + biq;
            const float* wp = ws + kbeg * 48 + js * 3;
            #pragma unroll 8
            for (int kk = 0; kk < 256; kk++) {
                ull h01 = *(const ull*)(hp);
                ull h23 = *(const ull*)(hp + 2);
                ull w0 = pk2(wp[0], wp[0]);
                ull w1 = pk2(wp[1], wp[1]);
                ull w2 = pk2(wp[2], wp[2]);
                fma2(a0, h01, w0); fma2(a1, h23, w0);
                fma2(a2, h01, w1); fma2(a3, h23, w1);
                fma2(a4, h01, w2); fma2(a5, h23, w2);
                hp += 36; wp += 48;
            }
        }
        {
            float* gp = ghs + kg * 1536;
            int j = js * 3;
            float2 v;
            v = upk2(a0); gp[(biq+0)*48 + j]   = v.x; gp[(biq+1)*48 + j]   = v.y;
            v = upk2(a1); gp[(biq+2)*48 + j]   = v.x; gp[(biq+3)*48 + j]   = v.y;
            v = upk2(a2); gp[(biq+0)*48 + j+1] = v.x; gp[(biq+1)*48 + j+1] = v.y;
            v = upk2(a3); gp[(biq+2)*48 + j+1] = v.x; gp[(biq+3)*48 + j+1] = v.y;
            v = upk2(a4); gp[(biq+0)*48 + j+2] = v.x; gp[(biq+1)*48 + j+2] = v.y;
            v = upk2(a5); gp[(biq+2)*48 + j+2] = v.x; gp[(biq+3)*48 + j+2] = v.y;
        }
        __syncthreads();

        // epilogue: 2 outputs per thread
        #pragma unroll
        for (int half = 0; half < 2; half++) {
            int bi  = bi_a + (half << 4);
            float gxr = half ? gxrB : gxrA;
            float gxz = half ? gxzB : gxzA;
            float gxn = half ? gxnB : gxnA;
            float ghr = ghs[bi*48 + dc_a]      + ghs[1536 + bi*48 + dc_a]      + bsh[dc_a];
            float ghz = ghs[bi*48 + 16 + dc_a] + ghs[1536 + bi*48 + 16 + dc_a] + bsh[16 + dc_a];
            float ghn = ghs[bi*48 + 32 + dc_a] + ghs[1536 + bi*48 + 32 + dc_a] + bsh[32 + dc_a];
            float r = 1.0f / (1.0f + __expf(-(gxr + ghr)));
            float z = 1.0f / (1.0f + __expf(-(gxz + ghz)));
            float n = tanhf(gxn + r * ghn);
            float hold = hs[d_a * 36 + bi];     // h_old from staged tile
            float hn = (1.0f - z) * n + z * hold;
            int big = b0 + bi;
            g_h[p ^ 1][big * 512 + d_a] = hn;
            g_e[(size_t)(big * 256 + t) * 512 + d_a] = hn;
        }

        // per-batch-group grid barrier (32 CTAs)
        __threadfence();
        __syncthreads();
        if (tid == 0) {
            unsigned target = (unsigned)(t + 1) * 32u;
            atomicAdd(&g_ctr4[bg], 1u);
            volatile unsigned* vc = &g_ctr4[bg];
            while (*vc < target) { }
        }
        __syncthreads();
        p ^= 1;
    }
}

// ---------------------------------------------------------------------------
// Fused head: out[m] = logsoftmax(f[m]) @ W_comb^T + b_comb
// ---------------------------------------------------------------------------
__global__ void __launch_bounds__(256)
k_final(const float* __restrict__ X, float* __restrict__ out) {
    __shared__ float Wc[NCLS * DD];
    __shared__ float ss[NCLS], bc[NCLS];
    int tid = threadIdx.x;
    for (int idx = tid; idx < NCLS * DD; idx += 256) Wc[idx] = g_Wc[idx];
    if (tid < NCLS) { ss[tid] = g_s[tid]; bc[tid] = g_bc[tid]; }
    __syncthreads();

    int w = tid >> 5, l = tid & 31;
    int m = (blockIdx.x << 3) + w;
    const float* xr = X + (size_t)m * DD;

    float f[16];
    #pragma unroll
    for (int i = 0; i < 16; i++) f[i] = xr[i * 32 + l];

    float mx = f[0];
    #pragma unroll
    for (int i = 1; i < 16; i++) mx = fmaxf(mx, f[i]);
    #pragma unroll
    for (int off = 16; off > 0; off >>= 1)
        mx = fmaxf(mx, __shfl_xor_sync(0xffffffffu, mx, off));

    float se = 0.0f;
    #pragma unroll
    for (int i = 0; i < 16; i++) se += __expf(f[i] - mx);
    #pragma unroll
    for (int off = 16; off > 0; off >>= 1)
        se += __shfl_xor_sync(0xffffffffu, se, off);
    float c = mx + __logf(se);

    #pragma unroll
    for (int n = 0; n < NCLS; n++) {
        float dot = 0.0f;
        const float* wr = Wc + n * DD;
        #pragma unroll
        for (int i = 0; i < 16; i++) dot += f[i] * wr[i * 32 + l];
        #pragma unroll
        for (int off = 16; off > 0; off >>= 1)
            dot += __shfl_xor_sync(0xffffffffu, dot, off);
        if (l == 0) out[m * NCLS + n] = dot - c * ss[n] + bc[n];
    }
}

// ---------------------------------------------------------------------------
// kernel_launch
// ---------------------------------------------------------------------------
extern "C" void kernel_launch(void* const* d_in, const int* in_sizes, int n_in,
                              void* d_out, int out_size) {
    (void)in_sizes; (void)out_size;
    if (n_in < 17) return;
    const float* x0     = (const float*)d_in[0];
    const float* W_ih   = (const float*)d_in[3];
    const float* W_hh   = (const float*)d_in[4];
    const float* b_ih   = (const float*)d_in[5];
    const float* b_hh   = (const float*)d_in[6];
    const float* W1     = (const float*)d_in[7];
    const float* bb1    = (const float*)d_in[8];
    const float* W2     = (const float*)d_in[9];
    const float* bb2    = (const float*)d_in[10];
    const float* W3     = (const float*)d_in[11];
    const float* bb3    = (const float*)d_in[12];
    const float* W_half = (const float*)d_in[13];
    const float* b_half = (const float*)d_in[14];
    const float* W_out  = (const float*)d_in[15];
    const float* b_out  = (const float*)d_in[16];
    float* out = (float*)d_out;

    float *gx, *e, *x1, *x2, *x3;
    cudaGetSymbolAddress((void**)&gx, g_gx);
    cudaGetSymbolAddress((void**)&e,  g_e);
    cudaGetSymbolAddress((void**)&x1, g_x1);
    cudaGetSymbolAddress((void**)&x2, g_x2);
    cudaGetSymbolAddress((void**)&x3, g_x3);

    cudaFuncSetAttribute(k_scan, cudaFuncAttributeMaxDynamicSharedMemorySize,
                         SCAN_SMEM_BYTES);

    k_init<<<256, 256>>>();
    k_prep1<<<14, 256>>>(W_half, W_out);
    k_prep2<<<1, 256>>>(W_out, b_half, b_out);

    // gx = x0(first half, permuted rows) @ W_ih^T + b_ih   [32768 x 1536]
    k_sgemm<<<dim3(12, 256), 256>>>(x0, W_ih, b_ih, gx, MROWS, 1536, 512, 0, 1);

    // GRU scan (256 steps), writes g_e
    k_scan<<<128, 256, SCAN_SMEM_BYTES>>>(W_hh, b_hh);

    // FFN
    k_sgemm<<<dim3(4, 256), 256>>>(e,  W1, bb1, x1, MROWS, 512, 512, 1, 0);
    k_sgemm<<<dim3(4, 256), 256>>>(x1, W2, bb2, x2, MROWS, 512, 512, 1, 0);
    k_sgemm<<<dim3(4, 256), 256>>>(x2, W3, bb3, x3, MROWS, 512, 512, 0, 0);

    // fused log_softmax + combined classifier head
    k_final<<<MROWS / 8, 256>>>(x3, out);
}

// round 5
// speedup vs baseline: 2.5241x; 1.2912x over previous
#include <cuda_runtime.h>
#include <cuda_bf16.h>
#include <cstddef>
#include <cstdint>

// Problem constants
#define BB     128
#define TT     512
#define HALF_T 256
#define DD     512
#define NCLS   7
#define MROWS  (BB * HALF_T)   // 32768 rows fed to FFN / head

typedef unsigned long long ull;

// ---------------------------------------------------------------------------
// Packed fp32 helpers (fma.rn.f32x2) — used by the scan
// ---------------------------------------------------------------------------
__device__ __forceinline__ ull pk2(float x, float y) {
    ull r;
    asm("mov.b64 %0, {%1, %2};" : "=l"(r)
        : "r"(__float_as_uint(x)), "r"(__float_as_uint(y)));
    return r;
}
__device__ __forceinline__ void fma2(ull& d, ull a, ull b) {
    asm("fma.rn.f32x2 %0, %1, %2, %0;" : "+l"(d) : "l"(a), "l"(b));
}
__device__ __forceinline__ float2 upk2(ull v) {
    unsigned lo, hi;
    asm("mov.b64 {%0, %1}, %2;" : "=r"(lo), "=r"(hi) : "l"(v));
    float2 r; r.x = __uint_as_float(lo); r.y = __uint_as_float(hi);
    return r;
}

// ---------------------------------------------------------------------------
// mma.sync / ldmatrix / cp.async helpers (baseline PTX, sm_100-safe)
// ---------------------------------------------------------------------------
__device__ __forceinline__ uint32_t smem_u32(const void* p) {
    uint32_t a;
    asm("{ .reg .u64 t; cvta.to.shared.u64 t, %1; cvt.u32.u64 %0, t; }"
        : "=r"(a) : "l"(p));
    return a;
}
__device__ __forceinline__ void ldsm4(uint32_t* r, uint32_t addr) {
    asm volatile("ldmatrix.sync.aligned.m8n8.x4.shared.b16 {%0,%1,%2,%3}, [%4];"
        : "=r"(r[0]), "=r"(r[1]), "=r"(r[2]), "=r"(r[3]) : "r"(addr));
}
__device__ __forceinline__ void mma_bf16(float* d, const uint32_t* a,
                                         uint32_t b0, uint32_t b1) {
    asm volatile("mma.sync.aligned.m16n8k16.row.col.f32.bf16.bf16.f32 "
        "{%0,%1,%2,%3}, {%4,%5,%6,%7}, {%8,%9}, {%0,%1,%2,%3};"
        : "+f"(d[0]), "+f"(d[1]), "+f"(d[2]), "+f"(d[3])
        : "r"(a[0]), "r"(a[1]), "r"(a[2]), "r"(a[3]), "r"(b0), "r"(b1));
}
__device__ __forceinline__ void cpasync16(uint32_t dst, const void* src) {
    asm volatile("cp.async.cg.shared.global [%0], [%1], 16;"
                 :: "r"(dst), "l"(src));
}
#define CP_COMMIT() asm volatile("cp.async.commit_group;" ::: "memory")

// ---------------------------------------------------------------------------
// Device scratch
// ---------------------------------------------------------------------------
__device__ float g_gx[MROWS * 1536];             // input projections (fp32)
__device__ float g_x3[MROWS * DD];               // FFN layer-3 output (fp32)
__device__ __nv_bfloat16 g_A0 [MROWS * 1024];    // x0 split planes (hi|lo)
__device__ __nv_bfloat16 g_e2 [MROWS * 1024];    // emotions split planes
__device__ __nv_bfloat16 g_x1b[MROWS * 1024];
__device__ __nv_bfloat16 g_x2b[MROWS * 1024];
__device__ __nv_bfloat16 g_Wih2[1536 * 1024];    // weight split planes
__device__ __nv_bfloat16 g_W12 [512 * 1024];
__device__ __nv_bfloat16 g_W22 [512 * 1024];
__device__ __nv_bfloat16 g_W32 [512 * 1024];
__device__ float g_h [2][BB * DD];               // double-buffered GRU state
__device__ float g_Wc[NCLS * DD];
__device__ float g_s [NCLS];
__device__ float g_bc[NCLS];
__device__ unsigned g_ctr4[4];                   // per-batch-group barriers

// ---------------------------------------------------------------------------
// Init
// ---------------------------------------------------------------------------
__global__ void k_init() {
    int idx = blockIdx.x * 256 + threadIdx.x;
    if (idx < BB * DD) g_h[0][idx] = 0.0f;
    if (idx < 4) g_ctr4[idx] = 0u;
}

// ---------------------------------------------------------------------------
// prep1/prep2: fold log_softmax + classifier head
// ---------------------------------------------------------------------------
__global__ void k_prep1(const float* __restrict__ W_half,
                        const float* __restrict__ W_out) {
    int idx = blockIdx.x * 256 + threadIdx.x;
    if (idx >= NCLS * DD) return;
    int n = idx / DD, k = idx % DD;
    float s = 0.0f;
    for (int j = 0; j < 256; j++)
        s += W_out[n * 256 + j] * W_half[j * DD + k];
    g_Wc[idx] = s;
}
__global__ void k_prep2(const float* __restrict__ W_out,
                        const float* __restrict__ b_half,
                        const float* __restrict__ b_out) {
    int tid = threadIdx.x;
    int w = tid >> 5, l = tid & 31;
    if (w < NCLS) {
        float s = 0.0f;
        #pragma unroll
        for (int i = 0; i < 16; i++) s += g_Wc[w * DD + i * 32 + l];
        #pragma unroll
        for (int off = 16; off > 0; off >>= 1)
            s += __shfl_xor_sync(0xffffffffu, s, off);
        if (l == 0) g_s[w] = s;
    }
    if (tid < NCLS) {
        float b = b_out[tid];
        for (int j = 0; j < 256; j++)
            b += W_out[tid * 256 + j] * b_half[j];
        g_bc[tid] = b;
    }
}

// ---------------------------------------------------------------------------
// k_split: fp32 [rows,512] -> bf16 hi/lo planes [rows,1024]
// ---------------------------------------------------------------------------
__global__ void k_split(const float* __restrict__ src,
                        __nv_bfloat16* __restrict__ dst,
                        int nrows, int perm) {
    int idx = blockIdx.x * 256 + threadIdx.x;
    if (idx >= nrows * 128) return;
    int r = idx >> 7, c4 = (idx & 127) << 2;
    size_t so = perm ? ((size_t)((r >> 8) * 512 + (r & 255)) * 512)
                     : ((size_t)r * 512);
    float4 v = *(const float4*)(src + so + c4);
    __nv_bfloat16 h[4], lo[4];
    float vv[4] = {v.x, v.y, v.z, v.w};
    #pragma unroll
    for (int i = 0; i < 4; i++) {
        h[i] = __float2bfloat16(vv[i]);
        lo[i] = __float2bfloat16(vv[i] - __bfloat162float(h[i]));
    }
    *(ull*)(dst + (size_t)r * 1024 + c4)       = *(ull*)h;
    *(ull*)(dst + (size_t)r * 1024 + 512 + c4) = *(ull*)lo;
}

// ---------------------------------------------------------------------------
// mma.sync bf16-split GEMM:  C[m,n] = act( sum_k A[m,k]*B[n,k] + bias[n] )
//   A planes [Mrows,1024] (hi|lo), B planes [N,1024] (hi|lo).
//   Expanded K' = 1536 via segments (hi,hi),(lo,hi),(hi,lo) -> 48 BK=32 chunks.
//   Tile 128x128, 8 warps (warp tile 32x64), cp.async double-buffered smem,
//   padded smem rows (80B) for conflict-free ldmatrix.
//   mode 0: fp32 out (stride Ntot), no act.  mode 1: tanh + bf16 planes out.
// ---------------------------------------------------------------------------
#define ROWB 80          // padded smem row: 32 bf16 (64B) + 16B pad
#define BUFB (128 * ROWB)

__global__ void __launch_bounds__(256, 2)
k_mma_gemm(const __nv_bfloat16* __restrict__ A,
           const __nv_bfloat16* __restrict__ Bw,
           const float* __restrict__ bias,
           void* __restrict__ Cout,
           int Ntot, int n_tiles, int mode) {
    __shared__ __align__(16) char smc[4 * BUFB];   // A0 A1 B0 B1
    uint32_t sbase = smem_u32(smc);
    int tid = threadIdx.x, wid = tid >> 5, lane = tid & 31;
    int m0 = (blockIdx.x / n_tiles) << 7;
    int n0 = (blockIdx.x % n_tiles) << 7;

    int sr = tid >> 2;            // staging row (0..63), second at +64
    int sc = tid & 3;             // 16B column chunk

    float acc[2][8][4];
    #pragma unroll
    for (int i = 0; i < 2; i++)
        #pragma unroll
        for (int j = 0; j < 8; j++)
            #pragma unroll
            for (int q = 0; q < 4; q++) acc[i][j][q] = 0.0f;

    // ---- async stage chunk c into buffer (c&1) ----
    auto issue = [&](int c) {
        int seg = c >> 4, kofs = (c & 15) << 5;
        int asel = (seg == 1) ? 512 : 0;
        int bsel = (seg == 2) ? 512 : 0;
        const __nv_bfloat16* Ag = A + (size_t)m0 * 1024 + asel + kofs;
        const __nv_bfloat16* Bg = Bw + (size_t)n0 * 1024 + bsel + kofs;
        uint32_t da = sbase + (uint32_t)(c & 1) * BUFB;
        uint32_t db = sbase + 2u * BUFB + (uint32_t)(c & 1) * BUFB;
        cpasync16(da + sr * ROWB + sc * 16,        Ag + (size_t)sr * 1024 + sc * 8);
        cpasync16(da + (sr + 64) * ROWB + sc * 16, Ag + (size_t)(sr + 64) * 1024 + sc * 8);
        cpasync16(db + sr * ROWB + sc * 16,        Bg + (size_t)sr * 1024 + sc * 8);
        cpasync16(db + (sr + 64) * ROWB + sc * 16, Bg + (size_t)(sr + 64) * 1024 + sc * 8);
    };

    issue(0); CP_COMMIT();
    issue(1); CP_COMMIT();

    int wm = wid & 3;             // m quadrant  (32 rows)
    int wn = wid >> 2;            // n half      (64 cols)
    uint32_t a_row  = (uint32_t)(wm * 32 + (lane & 15));
    uint32_t a_colb = (uint32_t)((lane >> 4) * 16);      // bytes
    uint32_t b_row  = (uint32_t)(wn * 64 + (lane & 7));
    uint32_t b_colb = (uint32_t)((lane >> 3) * 16);      // bytes, covers k0..31

    for (int c = 0; c < 48; c++) {
        if (c < 47) asm volatile("cp.async.wait_group 1;" ::: "memory");
        else        asm volatile("cp.async.wait_group 0;" ::: "memory");
        __syncthreads();

        uint32_t sA = sbase + (uint32_t)(c & 1) * BUFB;
        uint32_t sB = sbase + 2u * BUFB + (uint32_t)(c & 1) * BUFB;

        uint32_t bf[8][4];
        #pragma unroll
        for (int nt = 0; nt < 8; nt++)
            ldsm4(bf[nt], sB + (b_row + nt * 8) * ROWB + b_colb);

        #pragma unroll
        for (int ks = 0; ks < 2; ks++) {
            uint32_t af[2][4];
            ldsm4(af[0], sA + a_row * ROWB + ks * 32 + a_colb);
            ldsm4(af[1], sA + (a_row + 16) * ROWB + ks * 32 + a_colb);
            #pragma unroll
            for (int mi = 0; mi < 2; mi++)
                #pragma unroll
                for (int nt = 0; nt < 8; nt++)
                    mma_bf16(acc[mi][nt], af[mi], bf[nt][2 * ks], bf[nt][2 * ks + 1]);
        }
        __syncthreads();
        if (c + 2 < 48) issue(c + 2);
        CP_COMMIT();
    }

    // ---- epilogue ----
    int gid = lane >> 2, tig = lane & 3;
    float bv[16];
    #pragma unroll
    for (int nt = 0; nt < 8; nt++) {
        int col = n0 + wn * 64 + nt * 8 + 2 * tig;
        bv[nt * 2]     = bias[col];
        bv[nt * 2 + 1] = bias[col + 1];
    }
    #pragma unroll
    for (int mi = 0; mi < 2; mi++) {
        int mrow = m0 + wm * 32 + mi * 16 + gid;
        #pragma unroll
        for (int nt = 0; nt < 8; nt++) {
            int col = n0 + wn * 64 + nt * 8 + 2 * tig;
            float v0 = acc[mi][nt][0] + bv[nt * 2];
            float v1 = acc[mi][nt][1] + bv[nt * 2 + 1];
            float v2 = acc[mi][nt][2] + bv[nt * 2];
            float v3 = acc[mi][nt][3] + bv[nt * 2 + 1];
            if (mode == 0) {
                float* C = (float*)Cout;
                float2 p0 = {v0, v1}, p1 = {v2, v3};
                *(float2*)&C[(size_t)mrow * Ntot + col]       = p0;
                *(float2*)&C[(size_t)(mrow + 8) * Ntot + col] = p1;
            } else {
                __nv_bfloat16* C = (__nv_bfloat16*)Cout;
                v0 = tanhf(v0); v1 = tanhf(v1); v2 = tanhf(v2); v3 = tanhf(v3);
                __nv_bfloat16 h0 = __float2bfloat16(v0), h1 = __float2bfloat16(v1);
                __nv_bfloat16 h2 = __float2bfloat16(v2), h3 = __float2bfloat16(v3);
                __nv_bfloat16 l0 = __float2bfloat16(v0 - __bfloat162float(h0));
                __nv_bfloat16 l1 = __float2bfloat16(v1 - __bfloat162float(h1));
                __nv_bfloat16 l2 = __float2bfloat16(v2 - __bfloat162float(h2));
                __nv_bfloat16 l3 = __float2bfloat16(v3 - __bfloat162float(h3));
                __nv_bfloat162 ph0 = {h0, h1}, ph1 = {h2, h3};
                __nv_bfloat162 pl0 = {l0, l1}, pl1 = {l2, l3};
                *(__nv_bfloat162*)&C[(size_t)mrow * 1024 + col]             = ph0;
                *(__nv_bfloat162*)&C[(size_t)mrow * 1024 + 512 + col]       = pl0;
                *(__nv_bfloat162*)&C[(size_t)(mrow + 8) * 1024 + col]       = ph1;
                *(__nv_bfloat162*)&C[(size_t)(mrow + 8) * 1024 + 512 + col] = pl1;
            }
        }
    }
}

// ---------------------------------------------------------------------------
// Persistent GRU scan (proven round-3 core; epilogue emits bf16 hi/lo planes)
// ---------------------------------------------------------------------------
#define WS_F   (512 * 48)
#define HS_F   (512 * 36)
#define GHS_F  (2 * 32 * 48)
#define SCAN_SMEM_FLOATS (WS_F + HS_F + GHS_F + 64)
#define SCAN_SMEM_BYTES  (SCAN_SMEM_FLOATS * 4)

__global__ void __launch_bounds__(256, 1)
k_scan(const float* __restrict__ Whh, const float* __restrict__ bhh) {
    extern __shared__ char dynsm[];
    float* sm = (float*)dynsm;
    float* ws  = sm;
    float* hs  = sm + WS_F;
    float* ghs = hs + HS_F;
    float* bsh = ghs + GHS_F;

    int tid = threadIdx.x;
    int blk = blockIdx.x;
    int bg  = blk >> 5;
    int dg  = blk & 31;
    int d0  = dg << 4;
    int b0  = bg << 5;

    for (int idx = tid; idx < WS_F; idx += 256) {
        int k = idx / 48, j = idx - k * 48;
        int g = j >> 4, dc = j & 15;
        ws[idx] = Whh[(size_t)(g * 512 + d0 + dc) * 512 + k];
    }
    if (tid < 48) bsh[tid] = bhh[(tid >> 4) * 512 + d0 + (tid & 15)];
    __syncthreads();

    int kg  = tid >> 7;
    int ct  = tid & 127;
    int js  = ct & 15;
    int biq = ((ct >> 4) & 7) << 2;
    int kbeg = kg << 8;

    int bi_a = tid >> 4;
    int dc_a = tid & 15;
    int d_a  = d0 + dc_a;
    int p = 0;

    for (int t = 0; t < HALF_T; t++) {
        size_t rowA = (size_t)((b0 + bi_a) * 256 + t) * 1536;
        size_t rowB = (size_t)((b0 + bi_a + 16) * 256 + t) * 1536;
        float gxrA = __ldcg(g_gx + rowA + d_a);
        float gxzA = __ldcg(g_gx + rowA + 512 + d_a);
        float gxnA = __ldcg(g_gx + rowA + 1024 + d_a);
        float gxrB = __ldcg(g_gx + rowB + d_a);
        float gxzB = __ldcg(g_gx + rowB + 512 + d_a);
        float gxnB = __ldcg(g_gx + rowB + 1024 + d_a);

        const float* hsrc = g_h[p];

        for (int idx = tid; idx < 4096; idx += 256) {
            int bi = idx >> 7;
            int k4 = (idx & 127) << 2;
            float4 v = __ldcg((const float4*)(hsrc + (size_t)(b0 + bi) * 512 + k4));
            hs[(k4 + 0) * 36 + bi] = v.x;
            hs[(k4 + 1) * 36 + bi] = v.y;
            hs[(k4 + 2) * 36 + bi] = v.z;
            hs[(k4 + 3) * 36 + bi] = v.w;
        }
        __syncthreads();

        ull a0 = 0, a1 = 0, a2 = 0, a3 = 0, a4 = 0, a5 = 0;
        {
            const float* hp = hs + kbeg * 36 + biq;
            const float* wp = ws + kbeg * 48 + js * 3;
            #pragma unroll 8
            for (int kk = 0; kk < 256; kk++) {
                ull h01 = *(const ull*)(hp);
                ull h23 = *(const ull*)(hp + 2);
                ull w0 = pk2(wp[0], wp[0]);
                ull w1 = pk2(wp[1], wp[1]);
                ull w2 = pk2(wp[2], wp[2]);
                fma2(a0, h01, w0); fma2(a1, h23, w0);
                fma2(a2, h01, w1); fma2(a3, h23, w1);
                fma2(a4, h01, w2); fma2(a5, h23, w2);
                hp += 36; wp += 48;
            }
        }
        {
            float* gp = ghs + kg * 1536;
            int j = js * 3;
            float2 v;
            v = upk2(a0); gp[(biq+0)*48 + j]   = v.x; gp[(biq+1)*48 + j]   = v.y;
            v = upk2(a1); gp[(biq+2)*48 + j]   = v.x; gp[(biq+3)*48 + j]   = v.y;
            v = upk2(a2); gp[(biq+0)*48 + j+1] = v.x; gp[(biq+1)*48 + j+1] = v.y;
            v = upk2(a3); gp[(biq+2)*48 + j+1] = v.x; gp[(biq+3)*48 + j+1] = v.y;
            v = upk2(a4); gp[(biq+0)*48 + j+2] = v.x; gp[(biq+1)*48 + j+2] = v.y;
            v = upk2(a5); gp[(biq+2)*48 + j+2] = v.x; gp[(biq+3)*48 + j+2] = v.y;
        }
        __syncthreads();

        #pragma unroll
        for (int half = 0; half < 2; half++) {
            int bi  = bi_a + (half << 4);
            float gxr = half ? gxrB : gxrA;
            float gxz = half ? gxzB : gxzA;
            float gxn = half ? gxnB : gxnA;
            float ghr = ghs[bi*48 + dc_a]      + ghs[1536 + bi*48 + dc_a]      + bsh[dc_a];
            float ghz = ghs[bi*48 + 16 + dc_a] + ghs[1536 + bi*48 + 16 + dc_a] + bsh[16 + dc_a];
            float ghn = ghs[bi*48 + 32 + dc_a] + ghs[1536 + bi*48 + 32 + dc_a] + bsh[32 + dc_a];
            float r = 1.0f / (1.0f + __expf(-(gxr + ghr)));
            float z = 1.0f / (1.0f + __expf(-(gxz + ghz)));
            float n = tanhf(gxn + r * ghn);
            float hold = hs[d_a * 36 + bi];
            float hn = (1.0f - z) * n + z * hold;
            int big = b0 + bi;
            g_h[p ^ 1][big * 512 + d_a] = hn;
            size_t erow = (size_t)(big * 256 + t) * 1024;
            __nv_bfloat16 hi = __float2bfloat16(hn);
            float lof = hn - __bfloat162float(hi);
            g_e2[erow + d_a]       = hi;
            g_e2[erow + 512 + d_a] = __float2bfloat16(lof);
        }

        __threadfence();
        __syncthreads();
        if (tid == 0) {
            unsigned target = (unsigned)(t + 1) * 32u;
            atomicAdd(&g_ctr4[bg], 1u);
            volatile unsigned* vc = &g_ctr4[bg];
            while (*vc < target) { }
        }
        __syncthreads();
        p ^= 1;
    }
}

// ---------------------------------------------------------------------------
// Fused head: out[m] = logsoftmax(f[m]) @ W_comb^T + b_comb
// ---------------------------------------------------------------------------
__global__ void __launch_bounds__(256)
k_final(const float* __restrict__ X, float* __restrict__ out) {
    __shared__ float Wc[NCLS * DD];
    __shared__ float ss[NCLS], bc[NCLS];
    int tid = threadIdx.x;
    for (int idx = tid; idx < NCLS * DD; idx += 256) Wc[idx] = g_Wc[idx];
    if (tid < NCLS) { ss[tid] = g_s[tid]; bc[tid] = g_bc[tid]; }
    __syncthreads();

    int w = tid >> 5, l = tid & 31;
    int m = (blockIdx.x << 3) + w;
    const float* xr = X + (size_t)m * DD;

    float f[16];
    #pragma unroll
    for (int i = 0; i < 16; i++) f[i] = xr[i * 32 + l];

    float mx = f[0];
    #pragma unroll
    for (int i = 1; i < 16; i++) mx = fmaxf(mx, f[i]);
    #pragma unroll
    for (int off = 16; off > 0; off >>= 1)
        mx = fmaxf(mx, __shfl_xor_sync(0xffffffffu, mx, off));

    float se = 0.0f;
    #pragma unroll
    for (int i = 0; i < 16; i++) se += __expf(f[i] - mx);
    #pragma unroll
    for (int off = 16; off > 0; off >>= 1)
        se += __shfl_xor_sync(0xffffffffu, se, off);
    float c = mx + __logf(se);

    #pragma unroll
    for (int n = 0; n < NCLS; n++) {
        float dot = 0.0f;
        const float* wr = Wc + n * DD;
        #pragma unroll
        for (int i = 0; i < 16; i++) dot += f[i] * wr[i * 32 + l];
        #pragma unroll
        for (int off = 16; off > 0; off >>= 1)
            dot += __shfl_xor_sync(0xffffffffu, dot, off);
        if (l == 0) out[m * NCLS + n] = dot - c * ss[n] + bc[n];
    }
}

// ---------------------------------------------------------------------------
// kernel_launch
// ---------------------------------------------------------------------------
extern "C" void kernel_launch(void* const* d_in, const int* in_sizes, int n_in,
                              void* d_out, int out_size) {
    (void)in_sizes; (void)out_size;
    if (n_in < 17) return;
    const float* x0     = (const float*)d_in[0];
    const float* W_ih   = (const float*)d_in[3];
    const float* W_hh   = (const float*)d_in[4];
    const float* b_ih   = (const float*)d_in[5];
    const float* b_hh   = (const float*)d_in[6];
    const float* W1     = (const float*)d_in[7];
    const float* bb1    = (const float*)d_in[8];
    const float* W2     = (const float*)d_in[9];
    const float* bb2    = (const float*)d_in[10];
    const float* W3     = (const float*)d_in[11];
    const float* bb3    = (const float*)d_in[12];
    const float* W_half = (const float*)d_in[13];
    const float* b_half = (const float*)d_in[14];
    const float* W_out  = (const float*)d_in[15];
    const float* b_out  = (const float*)d_in[16];
    float* out = (float*)d_out;

    float *gx, *x3;
    __nv_bfloat16 *A0, *e2, *x1b, *x2b, *Wih2, *W12, *W22, *W32;
    cudaGetSymbolAddress((void**)&gx,   g_gx);
    cudaGetSymbolAddress((void**)&x3,   g_x3);
    cudaGetSymbolAddress((void**)&A0,   g_A0);
    cudaGetSymbolAddress((void**)&e2,   g_e2);
    cudaGetSymbolAddress((void**)&x1b,  g_x1b);
    cudaGetSymbolAddress((void**)&x2b,  g_x2b);
    cudaGetSymbolAddress((void**)&Wih2, g_Wih2);
    cudaGetSymbolAddress((void**)&W12,  g_W12);
    cudaGetSymbolAddress((void**)&W22,  g_W22);
    cudaGetSymbolAddress((void**)&W32,  g_W32);

    cudaFuncSetAttribute(k_scan, cudaFuncAttributeMaxDynamicSharedMemorySize,
                         SCAN_SMEM_BYTES);

    k_init<<<256, 256>>>();
    k_prep1<<<14, 256>>>(W_half, W_out);
    k_prep2<<<1, 256>>>(W_out, b_half, b_out);

    // fp32 -> bf16 hi/lo plane conversions
    k_split<<<(MROWS * 128) / 256, 256>>>(x0, A0, MROWS, 1);
    k_split<<<(1536 * 128) / 256, 256>>>(W_ih, Wih2, 1536, 0);
    k_split<<<(512 * 128) / 256, 256>>>(W1, W12, 512, 0);
    k_split<<<(512 * 128) / 256, 256>>>(W2, W22, 512, 0);
    k_split<<<(512 * 128) / 256, 256>>>(W3, W32, 512, 0);

    // gx = x0 @ W_ih^T + b_ih   [32768 x 1536]  (mma.sync, fp32 out)
    k_mma_gemm<<<256 * 12, 256>>>(A0, Wih2, b_ih, gx, 1536, 12, 0);

    // GRU scan (256 steps) -> e2 planes
    k_scan<<<128, 256, SCAN_SMEM_BYTES>>>(W_hh, b_hh);

    // FFN: tanh layers emit bf16 planes; layer 3 emits fp32
    k_mma_gemm<<<256 * 4, 256>>>(e2,  W12, bb1, x1b, 512, 4, 1);
    k_mma_gemm<<<256 * 4, 256>>>(x1b, W22, bb2, x2b, 512, 4, 1);
    k_mma_gemm<<<256 * 4, 256>>>(x2b, W32, bb3, x3,  512, 4, 0);

    // fused log_softmax + combined classifier head
    k_final<<<MROWS / 8, 256>>>(x3, out);
}

// round 6
// speedup vs baseline: 3.6869x; 1.4607x over previous
#include <cuda_runtime.h>
#include <cuda_bf16.h>
#include <cstddef>
#include <cstdint>

// Problem constants
#define BB     128
#define TT     512
#define HALF_T 256
#define DD     512
#define NCLS   7
#define MROWS  (BB * HALF_T)   // 32768 rows fed to FFN / head

typedef unsigned long long ull;

// ---------------------------------------------------------------------------
// mma.sync / ldmatrix / cp.async helpers (baseline PTX, sm_100-safe)
// ---------------------------------------------------------------------------
__device__ __forceinline__ uint32_t smem_u32(const void* p) {
    uint32_t a;
    asm("{ .reg .u64 t; cvta.to.shared.u64 t, %1; cvt.u32.u64 %0, t; }"
        : "=r"(a) : "l"(p));
    return a;
}
__device__ __forceinline__ void ldsm4(uint32_t* r, uint32_t addr) {
    asm volatile("ldmatrix.sync.aligned.m8n8.x4.shared.b16 {%0,%1,%2,%3}, [%4];"
        : "=r"(r[0]), "=r"(r[1]), "=r"(r[2]), "=r"(r[3]) : "r"(addr));
}
__device__ __forceinline__ void mma_bf16(float* d, const uint32_t* a,
                                         uint32_t b0, uint32_t b1) {
    asm volatile("mma.sync.aligned.m16n8k16.row.col.f32.bf16.bf16.f32 "
        "{%0,%1,%2,%3}, {%4,%5,%6,%7}, {%8,%9}, {%0,%1,%2,%3};"
        : "+f"(d[0]), "+f"(d[1]), "+f"(d[2]), "+f"(d[3])
        : "r"(a[0]), "r"(a[1]), "r"(a[2]), "r"(a[3]), "r"(b0), "r"(b1));
}
__device__ __forceinline__ void cpasync16(uint32_t dst, const void* src) {
    asm volatile("cp.async.cg.shared.global [%0], [%1], 16;"
                 :: "r"(dst), "l"(src));
}
#define CP_COMMIT() asm volatile("cp.async.commit_group;" ::: "memory")

// ---------------------------------------------------------------------------
// Device scratch
// ---------------------------------------------------------------------------
__device__ float g_gx[MROWS * 1536];             // input projections (fp32)
__device__ float g_x3[MROWS * DD];               // FFN layer-3 output (fp32)
__device__ __nv_bfloat16 g_A0 [MROWS * 1024];    // x0 split planes (hi|lo)
__device__ __nv_bfloat16 g_e2 [MROWS * 1024];    // emotions split planes
__device__ __nv_bfloat16 g_x1b[MROWS * 1024];
__device__ __nv_bfloat16 g_x2b[MROWS * 1024];
__device__ __nv_bfloat16 g_Wih2[1536 * 1024];    // weight split planes
__device__ __nv_bfloat16 g_W12 [512 * 1024];
__device__ __nv_bfloat16 g_W22 [512 * 1024];
__device__ __nv_bfloat16 g_W32 [512 * 1024];
__device__ __nv_bfloat16 g_h2[2 * BB * 1024];    // GRU h as bf16 hi|lo planes
__device__ float g_Wc[NCLS * DD];
__device__ float g_s [NCLS];
__device__ float g_bc[NCLS];
__device__ unsigned g_ctr4[4];                   // per-batch-group barriers

// ---------------------------------------------------------------------------
// Init: zero h planes buffer 0 + barrier counters (reset every graph replay)
// ---------------------------------------------------------------------------
__global__ void k_init() {
    int idx = blockIdx.x * 256 + threadIdx.x;   // 65536 threads
    if (idx < BB * 1024 / 2) {
        ((__nv_bfloat162*)g_h2)[idx] = __nv_bfloat162{__nv_bfloat16(0.f),
                                                      __nv_bfloat16(0.f)};
    }
    if (idx < 4) g_ctr4[idx] = 0u;
}

// ---------------------------------------------------------------------------
// prep1/prep2: fold log_softmax + classifier head
// ---------------------------------------------------------------------------
__global__ void k_prep1(const float* __restrict__ W_half,
                        const float* __restrict__ W_out) {
    int idx = blockIdx.x * 256 + threadIdx.x;
    if (idx >= NCLS * DD) return;
    int n = idx / DD, k = idx % DD;
    float s = 0.0f;
    for (int j = 0; j < 256; j++)
        s += W_out[n * 256 + j] * W_half[j * DD + k];
    g_Wc[idx] = s;
}
__global__ void k_prep2(const float* __restrict__ W_out,
                        const float* __restrict__ b_half,
                        const float* __restrict__ b_out) {
    int tid = threadIdx.x;
    int w = tid >> 5, l = tid & 31;
    if (w < NCLS) {
        float s = 0.0f;
        #pragma unroll
        for (int i = 0; i < 16; i++) s += g_Wc[w * DD + i * 32 + l];
        #pragma unroll
        for (int off = 16; off > 0; off >>= 1)
            s += __shfl_xor_sync(0xffffffffu, s, off);
        if (l == 0) g_s[w] = s;
    }
    if (tid < NCLS) {
        float b = b_out[tid];
        for (int j = 0; j < 256; j++)
            b += W_out[tid * 256 + j] * b_half[j];
        g_bc[tid] = b;
    }
}

// ---------------------------------------------------------------------------
// k_split: fp32 [rows,512] -> bf16 hi/lo planes [rows,1024]
// ---------------------------------------------------------------------------
__global__ void k_split(const float* __restrict__ src,
                        __nv_bfloat16* __restrict__ dst,
                        int nrows, int perm) {
    int idx = blockIdx.x * 256 + threadIdx.x;
    if (idx >= nrows * 128) return;
    int r = idx >> 7, c4 = (idx & 127) << 2;
    size_t so = perm ? ((size_t)((r >> 8) * 512 + (r & 255)) * 512)
                     : ((size_t)r * 512);
    float4 v = *(const float4*)(src + so + c4);
    __nv_bfloat16 h[4], lo[4];
    float vv[4] = {v.x, v.y, v.z, v.w};
    #pragma unroll
    for (int i = 0; i < 4; i++) {
        h[i] = __float2bfloat16(vv[i]);
        lo[i] = __float2bfloat16(vv[i] - __bfloat162float(h[i]));
    }
    *(ull*)(dst + (size_t)r * 1024 + c4)       = *(ull*)h;
    *(ull*)(dst + (size_t)r * 1024 + 512 + c4) = *(ull*)lo;
}

// ---------------------------------------------------------------------------
// mma.sync bf16-split GEMM (proven round-5 kernel, unchanged)
// ---------------------------------------------------------------------------
#define ROWB 80          // padded smem row: 32 bf16 (64B) + 16B pad
#define BUFB (128 * ROWB)

__global__ void __launch_bounds__(256, 2)
k_mma_gemm(const __nv_bfloat16* __restrict__ A,
           const __nv_bfloat16* __restrict__ Bw,
           const float* __restrict__ bias,
           void* __restrict__ Cout,
           int Ntot, int n_tiles, int mode) {
    __shared__ __align__(16) char smc[4 * BUFB];   // A0 A1 B0 B1
    uint32_t sbase = smem_u32(smc);
    int tid = threadIdx.x, wid = tid >> 5, lane = tid & 31;
    int m0 = (blockIdx.x / n_tiles) << 7;
    int n0 = (blockIdx.x % n_tiles) << 7;

    int sr = tid >> 2;
    int sc = tid & 3;

    float acc[2][8][4];
    #pragma unroll
    for (int i = 0; i < 2; i++)
        #pragma unroll
        for (int j = 0; j < 8; j++)
            #pragma unroll
            for (int q = 0; q < 4; q++) acc[i][j][q] = 0.0f;

    auto issue = [&](int c) {
        int seg = c >> 4, kofs = (c & 15) << 5;
        int asel = (seg == 1) ? 512 : 0;
        int bsel = (seg == 2) ? 512 : 0;
        const __nv_bfloat16* Ag = A + (size_t)m0 * 1024 + asel + kofs;
        const __nv_bfloat16* Bg = Bw + (size_t)n0 * 1024 + bsel + kofs;
        uint32_t da = sbase + (uint32_t)(c & 1) * BUFB;
        uint32_t db = sbase + 2u * BUFB + (uint32_t)(c & 1) * BUFB;
        cpasync16(da + sr * ROWB + sc * 16,        Ag + (size_t)sr * 1024 + sc * 8);
        cpasync16(da + (sr + 64) * ROWB + sc * 16, Ag + (size_t)(sr + 64) * 1024 + sc * 8);
        cpasync16(db + sr * ROWB + sc * 16,        Bg + (size_t)sr * 1024 + sc * 8);
        cpasync16(db + (sr + 64) * ROWB + sc * 16, Bg + (size_t)(sr + 64) * 1024 + sc * 8);
    };

    issue(0); CP_COMMIT();
    issue(1); CP_COMMIT();

    int wm = wid & 3;
    int wn = wid >> 2;
    uint32_t a_row  = (uint32_t)(wm * 32 + (lane & 15));
    uint32_t a_colb = (uint32_t)((lane >> 4) * 16);
    uint32_t b_row  = (uint32_t)(wn * 64 + (lane & 7));
    uint32_t b_colb = (uint32_t)((lane >> 3) * 16);

    for (int c = 0; c < 48; c++) {
        if (c < 47) asm volatile("cp.async.wait_group 1;" ::: "memory");
        else        asm volatile("cp.async.wait_group 0;" ::: "memory");
        __syncthreads();

        uint32_t sA = sbase + (uint32_t)(c & 1) * BUFB;
        uint32_t sB = sbase + 2u * BUFB + (uint32_t)(c & 1) * BUFB;

        uint32_t bf[8][4];
        #pragma unroll
        for (int nt = 0; nt < 8; nt++)
            ldsm4(bf[nt], sB + (b_row + nt * 8) * ROWB + b_colb);

        #pragma unroll
        for (int ks = 0; ks < 2; ks++) {
            uint32_t af[2][4];
            ldsm4(af[0], sA + a_row * ROWB + ks * 32 + a_colb);
            ldsm4(af[1], sA + (a_row + 16) * ROWB + ks * 32 + a_colb);
            #pragma unroll
            for (int mi = 0; mi < 2; mi++)
                #pragma unroll
                for (int nt = 0; nt < 8; nt++)
                    mma_bf16(acc[mi][nt], af[mi], bf[nt][2 * ks], bf[nt][2 * ks + 1]);
        }
        __syncthreads();
        if (c + 2 < 48) issue(c + 2);
        CP_COMMIT();
    }

    int gid = lane >> 2, tig = lane & 3;
    float bv[16];
    #pragma unroll
    for (int nt = 0; nt < 8; nt++) {
        int col = n0 + wn * 64 + nt * 8 + 2 * tig;
        bv[nt * 2]     = bias[col];
        bv[nt * 2 + 1] = bias[col + 1];
    }
    #pragma unroll
    for (int mi = 0; mi < 2; mi++) {
        int mrow = m0 + wm * 32 + mi * 16 + gid;
        #pragma unroll
        for (int nt = 0; nt < 8; nt++) {
            int col = n0 + wn * 64 + nt * 8 + 2 * tig;
            float v0 = acc[mi][nt][0] + bv[nt * 2];
            float v1 = acc[mi][nt][1] + bv[nt * 2 + 1];
            float v2 = acc[mi][nt][2] + bv[nt * 2];
            float v3 = acc[mi][nt][3] + bv[nt * 2 + 1];
            if (mode == 0) {
                float* C = (float*)Cout;
                float2 p0 = {v0, v1}, p1 = {v2, v3};
                *(float2*)&C[(size_t)mrow * Ntot + col]       = p0;
                *(float2*)&C[(size_t)(mrow + 8) * Ntot + col] = p1;
            } else {
                __nv_bfloat16* C = (__nv_bfloat16*)Cout;
                v0 = tanhf(v0); v1 = tanhf(v1); v2 = tanhf(v2); v3 = tanhf(v3);
                __nv_bfloat16 h0 = __float2bfloat16(v0), h1 = __float2bfloat16(v1);
                __nv_bfloat16 h2 = __float2bfloat16(v2), h3 = __float2bfloat16(v3);
                __nv_bfloat16 l0 = __float2bfloat16(v0 - __bfloat162float(h0));
                __nv_bfloat16 l1 = __float2bfloat16(v1 - __bfloat162float(h1));
                __nv_bfloat16 l2 = __float2bfloat16(v2 - __bfloat162float(h2));
                __nv_bfloat16 l3 = __float2bfloat16(v3 - __bfloat162float(h3));
                __nv_bfloat162 ph0 = {h0, h1}, ph1 = {h2, h3};
                __nv_bfloat162 pl0 = {l0, l1}, pl1 = {l2, l3};
                *(__nv_bfloat162*)&C[(size_t)mrow * 1024 + col]             = ph0;
                *(__nv_bfloat162*)&C[(size_t)mrow * 1024 + 512 + col]       = pl0;
                *(__nv_bfloat162*)&C[(size_t)(mrow + 8) * 1024 + col]       = ph1;
                *(__nv_bfloat162*)&C[(size_t)(mrow + 8) * 1024 + 512 + col] = pl1;
            }
        }
    }
}

// ---------------------------------------------------------------------------
// Persistent GRU scan with mma.sync step GEMM.
//   128 CTAs: 4 batch-groups x 32 d-groups. CTA owns 32 batches x 16 d-cols.
//   Per CTA: gh[48 x 32] = W_slice[48 x 512] @ h^T, bf16-split 3 passes,
//   W planes resident in smem (loaded once), h exchanged as bf16 hi/lo
//   planes via gmem (cp.async in, plane stores out).
// ---------------------------------------------------------------------------
#define SC_STRIDE 520                            // bf16 elems/row -> 1040 B
#define SC_W_BYTES (96 * SC_STRIDE * 2)          // 99840
#define SC_H_BYTES (64 * SC_STRIDE * 2)          // 66560
#define SC_GH_F    (48 * 33)
#define SCAN_SMEM_BYTES (SC_W_BYTES + SC_H_BYTES + SC_GH_F * 4 + 256)

__global__ void __launch_bounds__(256, 1)
k_scan(const float* __restrict__ Whh, const float* __restrict__ bhh) {
    extern __shared__ char dynsm[];
    __nv_bfloat16* ws  = (__nv_bfloat16*)dynsm;
    __nv_bfloat16* hsb = (__nv_bfloat16*)(dynsm + SC_W_BYTES);
    float* gh  = (float*)(dynsm + SC_W_BYTES + SC_H_BYTES);
    float* bsh = gh + SC_GH_F;
    uint32_t ws_u = smem_u32(ws);
    uint32_t hs_u = smem_u32(hsb);

    int tid = threadIdx.x, wid = tid >> 5, lane = tid & 31;
    int blk = blockIdx.x;
    int bg = blk >> 5, dg = blk & 31;
    int d0 = dg << 4, b0 = bg << 5;

    // Load W slice once, split into bf16 hi/lo plane rows.
    for (int i = tid; i < 48 * 512; i += 256) {
        int j = i >> 9, k = i & 511;            // j = gate*16 + dc
        int g = j >> 4, dc = j & 15;
        float w = Whh[(size_t)(g * 512 + d0 + dc) * 512 + k];
        __nv_bfloat16 hi = __float2bfloat16(w);
        __nv_bfloat16 lo = __float2bfloat16(w - __bfloat162float(hi));
        ws[j * SC_STRIDE + k]        = hi;
        ws[(48 + j) * SC_STRIDE + k] = lo;
    }
    if (tid < 48) bsh[tid] = bhh[(tid >> 4) * 512 + d0 + (tid & 15)];
    __syncthreads();

    int mt = wid % 3, nh = wid / 3;             // mma mapping (wid < 6)
    int srow = tid >> 2;                        // staging row 0..63
    int scol = (tid & 3) << 7;                  // bf16 col base (0/128/256/384)
    int splane = srow >> 5, sbatch = b0 + (srow & 31);
    uint32_t sdst = hs_u + (uint32_t)srow * 1040 + (uint32_t)scol * 2;

    int bi_a = tid >> 4;                        // epilogue: batches bi_a, +16
    int dc_a = tid & 15;
    int d_a = d0 + dc_a;
    int p = 0;

    for (int t = 0; t < HALF_T; t++) {
        // prefetch gx gate values (overlaps staging)
        size_t rowA = ((size_t)(b0 + bi_a) * 256 + t) * 1536;
        size_t rowB = ((size_t)(b0 + bi_a + 16) * 256 + t) * 1536;
        float gxrA = __ldcg(g_gx + rowA + d_a);
        float gxzA = __ldcg(g_gx + rowA + 512 + d_a);
        float gxnA = __ldcg(g_gx + rowA + 1024 + d_a);
        float gxrB = __ldcg(g_gx + rowB + d_a);
        float gxzB = __ldcg(g_gx + rowB + 512 + d_a);
        float gxnB = __ldcg(g_gx + rowB + 1024 + d_a);

        // stage h planes [64 rows x 512 bf16] via cp.async (L2-coherent)
        {
            const __nv_bfloat16* src = g_h2 + ((size_t)p * BB + sbatch) * 1024
                                     + splane * 512 + scol;
            #pragma unroll
            for (int j = 0; j < 16; j++)
                cpasync16(sdst + j * 16, src + j * 8);
        }
        CP_COMMIT();
        asm volatile("cp.async.wait_group 0;" ::: "memory");
        __syncthreads();

        // mma: gh[48 x 32], 3 split passes, warps 0..5
        float acc[2][4];
        if (wid < 6) {
            #pragma unroll
            for (int nt = 0; nt < 2; nt++)
                #pragma unroll
                for (int q = 0; q < 4; q++) acc[nt][q] = 0.0f;
            #pragma unroll
            for (int pass = 0; pass < 3; pass++) {
                uint32_t ab = ws_u + (uint32_t)(((pass == 1 ? 48 : 0) + mt * 16
                              + (lane & 15)) * 1040) + ((lane >> 4) << 4);
                uint32_t bb = hs_u + (uint32_t)(((pass == 2 ? 32 : 0) + nh * 16
                              + (lane & 7)) * 1040) + ((lane >> 3) << 4);
                #pragma unroll 4
                for (int k32 = 0; k32 < 16; k32++) {
                    int kb = k32 << 6;
                    uint32_t af0[4], af1[4], bf0[4], bf1[4];
                    ldsm4(af0, ab + kb);
                    ldsm4(af1, ab + kb + 32);
                    ldsm4(bf0, bb + kb);
                    ldsm4(bf1, bb + kb + 8 * 1040);
                    mma_bf16(acc[0], af0, bf0[0], bf0[1]);
                    mma_bf16(acc[1], af0, bf1[0], bf1[1]);
                    mma_bf16(acc[0], af1, bf0[2], bf0[3]);
                    mma_bf16(acc[1], af1, bf1[2], bf1[3]);
                }
            }
            // write gh fragments
            int r = lane >> 2, c = (lane & 3) << 1;
            #pragma unroll
            for (int nt = 0; nt < 2; nt++) {
                int n = nh * 16 + nt * 8 + c;
                int m = mt * 16 + r;
                gh[m * 33 + n]           = acc[nt][0];
                gh[m * 33 + n + 1]       = acc[nt][1];
                gh[(m + 8) * 33 + n]     = acc[nt][2];
                gh[(m + 8) * 33 + n + 1] = acc[nt][3];
            }
        }
        __syncthreads();

        // epilogue: 2 outputs per thread
        #pragma unroll
        for (int half = 0; half < 2; half++) {
            int bi = bi_a + (half << 4);
            float gxr = half ? gxrB : gxrA;
            float gxz = half ? gxzB : gxzA;
            float gxn = half ? gxnB : gxnA;
            float ghr = gh[dc_a * 33 + bi]        + bsh[dc_a];
            float ghz = gh[(16 + dc_a) * 33 + bi] + bsh[16 + dc_a];
            float ghn = gh[(32 + dc_a) * 33 + bi] + bsh[32 + dc_a];
            float r = 1.0f / (1.0f + __expf(-(gxr + ghr)));
            float z = 1.0f / (1.0f + __expf(-(gxz + ghz)));
            float n = tanhf(gxn + r * ghn);
            float hold = __bfloat162float(hsb[bi * SC_STRIDE + d_a])
                       + __bfloat162float(hsb[(32 + bi) * SC_STRIDE + d_a]);
            float hn = (1.0f - z) * n + z * hold;
            int big = b0 + bi;
            __nv_bfloat16 hi = __float2bfloat16(hn);
            __nv_bfloat16 lo = __float2bfloat16(hn - __bfloat162float(hi));
            size_t hrow = ((size_t)(p ^ 1) * BB + big) * 1024;
            g_h2[hrow + d_a]       = hi;
            g_h2[hrow + 512 + d_a] = lo;
            size_t erow = ((size_t)big * 256 + t) * 1024;
            g_e2[erow + d_a]       = hi;
            g_e2[erow + 512 + d_a] = lo;
        }

        // per-batch-group grid barrier
        __threadfence();
        __syncthreads();
        if (tid == 0) {
            unsigned target = (unsigned)(t + 1) * 32u;
            atomicAdd(&g_ctr4[bg], 1u);
            volatile unsigned* vc = &g_ctr4[bg];
            while (*vc < target) { }
        }
        __syncthreads();
        p ^= 1;
    }
}

// ---------------------------------------------------------------------------
// Fused head: out[m] = logsoftmax(f[m]) @ W_comb^T + b_comb
// ---------------------------------------------------------------------------
__global__ void __launch_bounds__(256)
k_final(const float* __restrict__ X, float* __restrict__ out) {
    __shared__ float Wc[NCLS * DD];
    __shared__ float ss[NCLS], bc[NCLS];
    int tid = threadIdx.x;
    for (int idx = tid; idx < NCLS * DD; idx += 256) Wc[idx] = g_Wc[idx];
    if (tid < NCLS) { ss[tid] = g_s[tid]; bc[tid] = g_bc[tid]; }
    __syncthreads();

    int w = tid >> 5, l = tid & 31;
    int m = (blockIdx.x << 3) + w;
    const float* xr = X + (size_t)m * DD;

    float f[16];
    #pragma unroll
    for (int i = 0; i < 16; i++) f[i] = xr[i * 32 + l];

    float mx = f[0];
    #pragma unroll
    for (int i = 1; i < 16; i++) mx = fmaxf(mx, f[i]);
    #pragma unroll
    for (int off = 16; off > 0; off >>= 1)
        mx = fmaxf(mx, __shfl_xor_sync(0xffffffffu, mx, off));

    float se = 0.0f;
    #pragma unroll
    for (int i = 0; i < 16; i++) se += __expf(f[i] - mx);
    #pragma unroll
    for (int off = 16; off > 0; off >>= 1)
        se += __shfl_xor_sync(0xffffffffu, se, off);
    float c = mx + __logf(se);

    #pragma unroll
    for (int n = 0; n < NCLS; n++) {
        float dot = 0.0f;
        const float* wr = Wc + n * DD;
        #pragma unroll
        for (int i = 0; i < 16; i++) dot += f[i] * wr[i * 32 + l];
        #pragma unroll
        for (int off = 16; off > 0; off >>= 1)
            dot += __shfl_xor_sync(0xffffffffu, dot, off);
        if (l == 0) out[m * NCLS + n] = dot - c * ss[n] + bc[n];
    }
}

// ---------------------------------------------------------------------------
// kernel_launch — ordered so k_scan is launch index 5 (ncu -s 5 -c 1 target)
// ---------------------------------------------------------------------------
extern "C" void kernel_launch(void* const* d_in, const int* in_sizes, int n_in,
                              void* d_out, int out_size) {
    (void)in_sizes; (void)out_size;
    if (n_in < 17) return;
    const float* x0     = (const float*)d_in[0];
    const float* W_ih   = (const float*)d_in[3];
    const float* W_hh   = (const float*)d_in[4];
    const float* b_ih   = (const float*)d_in[5];
    const float* b_hh   = (const float*)d_in[6];
    const float* W1     = (const float*)d_in[7];
    const float* bb1    = (const float*)d_in[8];
    const float* W2     = (const float*)d_in[9];
    const float* bb2    = (const float*)d_in[10];
    const float* W3     = (const float*)d_in[11];
    const float* bb3    = (const float*)d_in[12];
    const float* W_half = (const float*)d_in[13];
    const float* b_half = (const float*)d_in[14];
    const float* W_out  = (const float*)d_in[15];
    const float* b_out  = (const float*)d_in[16];
    float* out = (float*)d_out;

    float *gx, *x3;
    __nv_bfloat16 *A0, *e2, *x1b, *x2b, *Wih2, *W12, *W22, *W32;
    cudaGetSymbolAddress((void**)&gx,   g_gx);
    cudaGetSymbolAddress((void**)&x3,   g_x3);
    cudaGetSymbolAddress((void**)&A0,   g_A0);
    cudaGetSymbolAddress((void**)&e2,   g_e2);
    cudaGetSymbolAddress((void**)&x1b,  g_x1b);
    cudaGetSymbolAddress((void**)&x2b,  g_x2b);
    cudaGetSymbolAddress((void**)&Wih2, g_Wih2);
    cudaGetSymbolAddress((void**)&W12,  g_W12);
    cudaGetSymbolAddress((void**)&W22,  g_W22);
    cudaGetSymbolAddress((void**)&W32,  g_W32);

    cudaFuncSetAttribute(k_scan, cudaFuncAttributeMaxDynamicSharedMemorySize,
                         SCAN_SMEM_BYTES);

    // 0,1: input/weight splits needed by gx GEMM
    k_split<<<(MROWS * 128) / 256, 256>>>(x0, A0, MROWS, 1);
    k_split<<<(1536 * 128) / 256, 256>>>(W_ih, Wih2, 1536, 0);
    // 2: init h planes + barrier counters
    k_init<<<256, 256>>>();
    // 3: gx = x0 @ W_ih^T + b_ih   [32768 x 1536]
    k_mma_gemm<<<256 * 12, 256>>>(A0, Wih2, b_ih, gx, 1536, 12, 0);
    // 4: head fold (independent)
    k_prep1<<<14, 256>>>(W_half, W_out);
    // 5: GRU scan (PROFILED)
    k_scan<<<128, 256, SCAN_SMEM_BYTES>>>(W_hh, b_hh);
    // 6: head fold part 2
    k_prep2<<<1, 256>>>(W_out, b_half, b_out);
    // 7-9: FFN weight splits
    k_split<<<(512 * 128) / 256, 256>>>(W1, W12, 512, 0);
    k_split<<<(512 * 128) / 256, 256>>>(W2, W22, 512, 0);
    k_split<<<(512 * 128) / 256, 256>>>(W3, W32, 512, 0);
    // 10-12: FFN
    k_mma_gemm<<<256 * 4, 256>>>(e2,  W12, bb1, x1b, 512, 4, 1);
    k_mma_gemm<<<256 * 4, 256>>>(x1b, W22, bb2, x2b, 512, 4, 1);
    k_mma_gemm<<<256 * 4, 256>>>(x2b, W32, bb3, x3,  512, 4, 0);
    // 13: fused log_softmax + combined classifier head
    k_final<<<MROWS / 8, 256>>>(x3, out);
}

// round 7
// speedup vs baseline: 3.8534x; 1.0451x over previous
#include <cuda_runtime.h>
#include <cuda_bf16.h>
#include <cstddef>
#include <cstdint>

// Problem constants
#define BB     128
#define TT     512
#define HALF_T 256
#define DD     512
#define NCLS   7
#define MROWS  (BB * HALF_T)   // 32768 rows fed to FFN / head

typedef unsigned long long ull;

// ---------------------------------------------------------------------------
// mma.sync / ldmatrix / cp.async helpers (baseline PTX, sm_100-safe)
// ---------------------------------------------------------------------------
__device__ __forceinline__ uint32_t smem_u32(const void* p) {
    uint32_t a;
    asm("{ .reg .u64 t; cvta.to.shared.u64 t, %1; cvt.u32.u64 %0, t; }"
        : "=r"(a) : "l"(p));
    return a;
}
__device__ __forceinline__ void ldsm4(uint32_t* r, uint32_t addr) {
    asm volatile("ldmatrix.sync.aligned.m8n8.x4.shared.b16 {%0,%1,%2,%3}, [%4];"
        : "=r"(r[0]), "=r"(r[1]), "=r"(r[2]), "=r"(r[3]) : "r"(addr));
}
__device__ __forceinline__ void mma_bf16(float* d, const uint32_t* a,
                                         uint32_t b0, uint32_t b1) {
    asm volatile("mma.sync.aligned.m16n8k16.row.col.f32.bf16.bf16.f32 "
        "{%0,%1,%2,%3}, {%4,%5,%6,%7}, {%8,%9}, {%0,%1,%2,%3};"
        : "+f"(d[0]), "+f"(d[1]), "+f"(d[2]), "+f"(d[3])
        : "r"(a[0]), "r"(a[1]), "r"(a[2]), "r"(a[3]), "r"(b0), "r"(b1));
}
__device__ __forceinline__ void cpasync16(uint32_t dst, const void* src) {
    asm volatile("cp.async.cg.shared.global [%0], [%1], 16;"
                 :: "r"(dst), "l"(src));
}
#define CP_COMMIT() asm volatile("cp.async.commit_group;" ::: "memory")

// ---------------------------------------------------------------------------
// Device scratch
// ---------------------------------------------------------------------------
__device__ float g_gx[MROWS * 1536];             // input projections (fp32)
__device__ float g_x3[MROWS * DD];               // FFN layer-3 output (fp32)
__device__ __nv_bfloat16 g_A0 [MROWS * 1024];    // x0 split planes (hi|lo)
__device__ __nv_bfloat16 g_e2 [MROWS * 1024];    // emotions split planes
__device__ __nv_bfloat16 g_x1b[MROWS * 1024];
__device__ __nv_bfloat16 g_x2b[MROWS * 1024];
__device__ __nv_bfloat16 g_Wih2[1536 * 1024];    // weight split planes
__device__ __nv_bfloat16 g_W12 [512 * 1024];
__device__ __nv_bfloat16 g_W22 [512 * 1024];
__device__ __nv_bfloat16 g_W32 [512 * 1024];
__device__ __nv_bfloat16 g_h2[2 * BB * 1024];    // GRU h as bf16 hi|lo planes
__device__ float g_Wc[NCLS * DD];
__device__ float g_s [NCLS];
__device__ float g_bc[NCLS];
__device__ unsigned g_ctr4[4];                   // per-batch-group barriers

// ---------------------------------------------------------------------------
// Init: zero h planes buffer 0 + barrier counters (reset every graph replay)
// ---------------------------------------------------------------------------
__global__ void k_init() {
    int idx = blockIdx.x * 256 + threadIdx.x;   // 65536 threads
    if (idx < BB * 1024 / 2) {
        ((__nv_bfloat162*)g_h2)[idx] = __nv_bfloat162{__nv_bfloat16(0.f),
                                                      __nv_bfloat16(0.f)};
    }
    if (idx < 4) g_ctr4[idx] = 0u;
}

// ---------------------------------------------------------------------------
// prep1/prep2: fold log_softmax + classifier head
// ---------------------------------------------------------------------------
__global__ void k_prep1(const float* __restrict__ W_half,
                        const float* __restrict__ W_out) {
    int idx = blockIdx.x * 256 + threadIdx.x;
    if (idx >= NCLS * DD) return;
    int n = idx / DD, k = idx % DD;
    float s = 0.0f;
    for (int j = 0; j < 256; j++)
        s += W_out[n * 256 + j] * W_half[j * DD + k];
    g_Wc[idx] = s;
}
__global__ void k_prep2(const float* __restrict__ W_out,
                        const float* __restrict__ b_half,
                        const float* __restrict__ b_out) {
    int tid = threadIdx.x;
    int w = tid >> 5, l = tid & 31;
    if (w < NCLS) {
        float s = 0.0f;
        #pragma unroll
        for (int i = 0; i < 16; i++) s += g_Wc[w * DD + i * 32 + l];
        #pragma unroll
        for (int off = 16; off > 0; off >>= 1)
            s += __shfl_xor_sync(0xffffffffu, s, off);
        if (l == 0) g_s[w] = s;
    }
    if (tid < NCLS) {
        float b = b_out[tid];
        for (int j = 0; j < 256; j++)
            b += W_out[tid * 256 + j] * b_half[j];
        g_bc[tid] = b;
    }
}

// ---------------------------------------------------------------------------
// k_split: fp32 [rows,512] -> bf16 hi/lo planes [rows,1024]
// ---------------------------------------------------------------------------
__global__ void k_split(const float* __restrict__ src,
                        __nv_bfloat16* __restrict__ dst,
                        int nrows, int perm) {
    int idx = blockIdx.x * 256 + threadIdx.x;
    if (idx >= nrows * 128) return;
    int r = idx >> 7, c4 = (idx & 127) << 2;
    size_t so = perm ? ((size_t)((r >> 8) * 512 + (r & 255)) * 512)
                     : ((size_t)r * 512);
    float4 v = *(const float4*)(src + so + c4);
    __nv_bfloat16 h[4], lo[4];
    float vv[4] = {v.x, v.y, v.z, v.w};
    #pragma unroll
    for (int i = 0; i < 4; i++) {
        h[i] = __float2bfloat16(vv[i]);
        lo[i] = __float2bfloat16(vv[i] - __bfloat162float(h[i]));
    }
    *(ull*)(dst + (size_t)r * 1024 + c4)       = *(ull*)h;
    *(ull*)(dst + (size_t)r * 1024 + 512 + c4) = *(ull*)lo;
}

// ---------------------------------------------------------------------------
// mma.sync bf16-split GEMM, 3-stage cp.async pipeline, ONE sync per chunk.
//   C[m,n] = act( sum_k A[m,k]*B[n,k] + bias[n] ),  K' = 1536 (3 segments).
// ---------------------------------------------------------------------------
#define ROWB 80          // padded smem row: 32 bf16 (64B) + 16B pad
#define BUFB (128 * ROWB)
#define NST  3
#define GEMM_SMEM (2 * NST * BUFB)   // 61440

__global__ void __launch_bounds__(256, 2)
k_mma_gemm(const __nv_bfloat16* __restrict__ A,
           const __nv_bfloat16* __restrict__ Bw,
           const float* __restrict__ bias,
           void* __restrict__ Cout,
           int Ntot, int n_tiles, int mode) {
    extern __shared__ __align__(16) char smc[];
    uint32_t sbase = smem_u32(smc);
    int tid = threadIdx.x, wid = tid >> 5, lane = tid & 31;
    int m0 = (blockIdx.x / n_tiles) << 7;
    int n0 = (blockIdx.x % n_tiles) << 7;

    int sr = tid >> 2;
    int sc = tid & 3;

    float acc[2][8][4];
    #pragma unroll
    for (int i = 0; i < 2; i++)
        #pragma unroll
        for (int j = 0; j < 8; j++)
            #pragma unroll
            for (int q = 0; q < 4; q++) acc[i][j][q] = 0.0f;

    auto issue = [&](int c) {
        int seg = c >> 4, kofs = (c & 15) << 5;
        int asel = (seg == 1) ? 512 : 0;
        int bsel = (seg == 2) ? 512 : 0;
        const __nv_bfloat16* Ag = A + (size_t)m0 * 1024 + asel + kofs;
        const __nv_bfloat16* Bg = Bw + (size_t)n0 * 1024 + bsel + kofs;
        int buf = c % NST;
        uint32_t da = sbase + (uint32_t)buf * BUFB;
        uint32_t db = sbase + (uint32_t)(NST + buf) * BUFB;
        cpasync16(da + sr * ROWB + sc * 16,        Ag + (size_t)sr * 1024 + sc * 8);
        cpasync16(da + (sr + 64) * ROWB + sc * 16, Ag + (size_t)(sr + 64) * 1024 + sc * 8);
        cpasync16(db + sr * ROWB + sc * 16,        Bg + (size_t)sr * 1024 + sc * 8);
        cpasync16(db + (sr + 64) * ROWB + sc * 16, Bg + (size_t)(sr + 64) * 1024 + sc * 8);
        CP_COMMIT();
    };

    issue(0);
    issue(1);

    int wm = wid & 3;
    int wn = wid >> 2;
    uint32_t a_row  = (uint32_t)(wm * 32 + (lane & 15));
    uint32_t a_colb = (uint32_t)((lane >> 4) * 16);
    uint32_t b_row  = (uint32_t)(wn * 64 + (lane & 7));
    uint32_t b_colb = (uint32_t)((lane >> 3) * 16);

    for (int c = 0; c < 48; c++) {
        if (c < 47) asm volatile("cp.async.wait_group 1;" ::: "memory");
        else        asm volatile("cp.async.wait_group 0;" ::: "memory");
        __syncthreads();
        if (c + 2 < 48) issue(c + 2);

        int buf = c % NST;
        uint32_t sA = sbase + (uint32_t)buf * BUFB;
        uint32_t sB = sbase + (uint32_t)(NST + buf) * BUFB;

        uint32_t bf[8][4];
        #pragma unroll
        for (int nt = 0; nt < 8; nt++)
            ldsm4(bf[nt], sB + (b_row + nt * 8) * ROWB + b_colb);

        #pragma unroll
        for (int ks = 0; ks < 2; ks++) {
            uint32_t af[2][4];
            ldsm4(af[0], sA + a_row * ROWB + ks * 32 + a_colb);
            ldsm4(af[1], sA + (a_row + 16) * ROWB + ks * 32 + a_colb);
            #pragma unroll
            for (int mi = 0; mi < 2; mi++)
                #pragma unroll
                for (int nt = 0; nt < 8; nt++)
                    mma_bf16(acc[mi][nt], af[mi], bf[nt][2 * ks], bf[nt][2 * ks + 1]);
        }
    }

    int gid = lane >> 2, tig = lane & 3;
    float bv[16];
    #pragma unroll
    for (int nt = 0; nt < 8; nt++) {
        int col = n0 + wn * 64 + nt * 8 + 2 * tig;
        bv[nt * 2]     = bias[col];
        bv[nt * 2 + 1] = bias[col + 1];
    }
    #pragma unroll
    for (int mi = 0; mi < 2; mi++) {
        int mrow = m0 + wm * 32 + mi * 16 + gid;
        #pragma unroll
        for (int nt = 0; nt < 8; nt++) {
            int col = n0 + wn * 64 + nt * 8 + 2 * tig;
            float v0 = acc[mi][nt][0] + bv[nt * 2];
            float v1 = acc[mi][nt][1] + bv[nt * 2 + 1];
            float v2 = acc[mi][nt][2] + bv[nt * 2];
            float v3 = acc[mi][nt][3] + bv[nt * 2 + 1];
            if (mode == 0) {
                float* C = (float*)Cout;
                float2 p0 = {v0, v1}, p1 = {v2, v3};
                *(float2*)&C[(size_t)mrow * Ntot + col]       = p0;
                *(float2*)&C[(size_t)(mrow + 8) * Ntot + col] = p1;
            } else {
                __nv_bfloat16* C = (__nv_bfloat16*)Cout;
                v0 = tanhf(v0); v1 = tanhf(v1); v2 = tanhf(v2); v3 = tanhf(v3);
                __nv_bfloat16 h0 = __float2bfloat16(v0), h1 = __float2bfloat16(v1);
                __nv_bfloat16 h2 = __float2bfloat16(v2), h3 = __float2bfloat16(v3);
                __nv_bfloat16 l0 = __float2bfloat16(v0 - __bfloat162float(h0));
                __nv_bfloat16 l1 = __float2bfloat16(v1 - __bfloat162float(h1));
                __nv_bfloat16 l2 = __float2bfloat16(v2 - __bfloat162float(h2));
                __nv_bfloat16 l3 = __float2bfloat16(v3 - __bfloat162float(h3));
                __nv_bfloat162 ph0 = {h0, h1}, ph1 = {h2, h3};
                __nv_bfloat162 pl0 = {l0, l1}, pl1 = {l2, l3};
                *(__nv_bfloat162*)&C[(size_t)mrow * 1024 + col]             = ph0;
                *(__nv_bfloat162*)&C[(size_t)mrow * 1024 + 512 + col]       = pl0;
                *(__nv_bfloat162*)&C[(size_t)(mrow + 8) * 1024 + col]       = ph1;
                *(__nv_bfloat162*)&C[(size_t)(mrow + 8) * 1024 + 512 + col] = pl1;
            }
        }
    }
}

// ---------------------------------------------------------------------------
// Persistent GRU scan with mma.sync step GEMM.
//   hi/lo staging phases overlap the lo copy with the hhi mma passes;
//   fragment reuse: A-hi/A-lo/B-hi loaded once per k32 (8 mma), B-lo phase 4.
// ---------------------------------------------------------------------------
#define SC_STRIDE 520                            // bf16 elems/row -> 1040 B
#define SC_W_BYTES (96 * SC_STRIDE * 2)          // 99840
#define SC_H_BYTES (64 * SC_STRIDE * 2)          // 66560
#define SC_GH_F    (48 * 33)
#define SCAN_SMEM_BYTES (SC_W_BYTES + SC_H_BYTES + SC_GH_F * 4 + 256)

__global__ void __launch_bounds__(256, 1)
k_scan(const float* __restrict__ Whh, const float* __restrict__ bhh) {
    extern __shared__ char dynsm[];
    __nv_bfloat16* ws  = (__nv_bfloat16*)dynsm;
    __nv_bfloat16* hsb = (__nv_bfloat16*)(dynsm + SC_W_BYTES);
    float* gh  = (float*)(dynsm + SC_W_BYTES + SC_H_BYTES);
    float* bsh = gh + SC_GH_F;
    uint32_t ws_u = smem_u32(ws);
    uint32_t hs_u = smem_u32(hsb);

    int tid = threadIdx.x, wid = tid >> 5, lane = tid & 31;
    int blk = blockIdx.x;
    int bg = blk >> 5, dg = blk & 31;
    int d0 = dg << 4, b0 = bg << 5;

    // Load W slice once, split into bf16 hi/lo plane rows.
    for (int i = tid; i < 48 * 512; i += 256) {
        int j = i >> 9, k = i & 511;            // j = gate*16 + dc
        int g = j >> 4, dc = j & 15;
        float w = Whh[(size_t)(g * 512 + d0 + dc) * 512 + k];
        __nv_bfloat16 hi = __float2bfloat16(w);
        __nv_bfloat16 lo = __float2bfloat16(w - __bfloat162float(hi));
        ws[j * SC_STRIDE + k]        = hi;
        ws[(48 + j) * SC_STRIDE + k] = lo;
    }
    if (tid < 48) bsh[tid] = bhh[(tid >> 4) * 512 + d0 + (tid & 15)];
    __syncthreads();

    int mt = wid % 3, nh = wid / 3;             // mma mapping (wid < 6)
    int srow = tid >> 2;                        // staging row 0..63
    int scol = (tid & 3) << 7;                  // bf16 col base
    int splane = srow >> 5, sbatch = b0 + (srow & 31);
    uint32_t sdst = hs_u + (uint32_t)srow * 1040 + (uint32_t)scol * 2;

    // mma fragment addresses (constant per thread)
    uint32_t aw_hi = ws_u + (uint32_t)((mt * 16 + (lane & 15)) * 1040)
                   + ((lane >> 4) << 4);
    uint32_t aw_lo = aw_hi + 48u * 1040u;
    uint32_t bh_hi = hs_u + (uint32_t)((nh * 16 + (lane & 7)) * 1040)
                   + ((lane >> 3) << 4);
    uint32_t bh_lo = bh_hi + 32u * 1040u;

    int bi_a = tid >> 4;                        // epilogue: batches bi_a, +16
    int dc_a = tid & 15;
    int d_a = d0 + dc_a;
    int p = 0;

    for (int t = 0; t < HALF_T; t++) {
        // prefetch gx gate values (overlaps staging)
        size_t rowA = ((size_t)(b0 + bi_a) * 256 + t) * 1536;
        size_t rowB = ((size_t)(b0 + bi_a + 16) * 256 + t) * 1536;
        float gxrA = __ldcg(g_gx + rowA + d_a);
        float gxzA = __ldcg(g_gx + rowA + 512 + d_a);
        float gxnA = __ldcg(g_gx + rowA + 1024 + d_a);
        float gxrB = __ldcg(g_gx + rowB + d_a);
        float gxzB = __ldcg(g_gx + rowB + 512 + d_a);
        float gxnB = __ldcg(g_gx + rowB + 1024 + d_a);

        // stage h planes: tid<128 stages hi rows, tid>=128 stages lo rows
        {
            const __nv_bfloat16* src = g_h2 + ((size_t)p * BB + sbatch) * 1024
                                     + splane * 512 + scol;
            #pragma unroll
            for (int j = 0; j < 16; j++)
                cpasync16(sdst + j * 16, src + j * 8);
        }
        CP_COMMIT();
        if (tid < 128) asm volatile("cp.async.wait_group 0;" ::: "memory");
        __syncthreads();                         // hi plane visible

        // hi-phase mma: (Whi,hhi) + (Wlo,hhi), lo copies still in flight
        float acc[2][4];
        if (wid < 6) {
            #pragma unroll
            for (int nt = 0; nt < 2; nt++)
                #pragma unroll
                for (int q = 0; q < 4; q++) acc[nt][q] = 0.0f;
            #pragma unroll 4
            for (int k32 = 0; k32 < 16; k32++) {
                int kb = k32 << 6;
                uint32_t ah0[4], ah1[4], al0[4], al1[4], bf0[4], bf1[4];
                ldsm4(ah0, aw_hi + kb);
                ldsm4(ah1, aw_hi + kb + 32);
                ldsm4(al0, aw_lo + kb);
                ldsm4(al1, aw_lo + kb + 32);
                ldsm4(bf0, bh_hi + kb);
                ldsm4(bf1, bh_hi + kb + 8 * 1040);
                mma_bf16(acc[0], ah0, bf0[0], bf0[1]);
                mma_bf16(acc[1], ah0, bf1[0], bf1[1]);
                mma_bf16(acc[0], ah1, bf0[2], bf0[3]);
                mma_bf16(acc[1], ah1, bf1[2], bf1[3]);
                mma_bf16(acc[0], al0, bf0[0], bf0[1]);
                mma_bf16(acc[1], al0, bf1[0], bf1[1]);
                mma_bf16(acc[0], al1, bf0[2], bf0[3]);
                mma_bf16(acc[1], al1, bf1[2], bf1[3]);
            }
        }
        if (tid >= 128) asm volatile("cp.async.wait_group 0;" ::: "memory");
        __syncthreads();                         // lo plane visible

        if (wid < 6) {
            #pragma unroll 4
            for (int k32 = 0; k32 < 16; k32++) {
                int kb = k32 << 6;
                uint32_t ah0[4], ah1[4], bl0[4], bl1[4];
                ldsm4(ah0, aw_hi + kb);
                ldsm4(ah1, aw_hi + kb + 32);
                ldsm4(bl0, bh_lo + kb);
                ldsm4(bl1, bh_lo + kb + 8 * 1040);
                mma_bf16(acc[0], ah0, bl0[0], bl0[1]);
                mma_bf16(acc[1], ah0, bl1[0], bl1[1]);
                mma_bf16(acc[0], ah1, bl0[2], bl0[3]);
                mma_bf16(acc[1], ah1, bl1[2], bl1[3]);
            }
            // write gh fragments
            int r = lane >> 2, c = (lane & 3) << 1;
            #pragma unroll
            for (int nt = 0; nt < 2; nt++) {
                int n = nh * 16 + nt * 8 + c;
                int m = mt * 16 + r;
                gh[m * 33 + n]           = acc[nt][0];
                gh[m * 33 + n + 1]       = acc[nt][1];
                gh[(m + 8) * 33 + n]     = acc[nt][2];
                gh[(m + 8) * 33 + n + 1] = acc[nt][3];
            }
        }
        __syncthreads();

        // epilogue: 2 outputs per thread
        #pragma unroll
        for (int half = 0; half < 2; half++) {
            int bi = bi_a + (half << 4);
            float gxr = half ? gxrB : gxrA;
            float gxz = half ? gxzB : gxzA;
            float gxn = half ? gxnB : gxnA;
            float ghr = gh[dc_a * 33 + bi]        + bsh[dc_a];
            float ghz = gh[(16 + dc_a) * 33 + bi] + bsh[16 + dc_a];
            float ghn = gh[(32 + dc_a) * 33 + bi] + bsh[32 + dc_a];
            float r = 1.0f / (1.0f + __expf(-(gxr + ghr)));
            float z = 1.0f / (1.0f + __expf(-(gxz + ghz)));
            float n = tanhf(gxn + r * ghn);
            float hold = __bfloat162float(hsb[bi * SC_STRIDE + d_a])
                       + __bfloat162float(hsb[(32 + bi) * SC_STRIDE + d_a]);
            float hn = (1.0f - z) * n + z * hold;
            int big = b0 + bi;
            __nv_bfloat16 hi = __float2bfloat16(hn);
            __nv_bfloat16 lo = __float2bfloat16(hn - __bfloat162float(hi));
            if (t < HALF_T - 1) {
                size_t hrow = ((size_t)(p ^ 1) * BB + big) * 1024;
                g_h2[hrow + d_a]       = hi;
                g_h2[hrow + 512 + d_a] = lo;
            }
            size_t erow = ((size_t)big * 256 + t) * 1024;
            g_e2[erow + d_a]       = hi;
            g_e2[erow + 512 + d_a] = lo;
        }

        // per-batch-group grid barrier (skipped on the final step)
        if (t < HALF_T - 1) {
            __threadfence();
            __syncthreads();
            if (tid == 0) {
                unsigned target = (unsigned)(t + 1) * 32u;
                atomicAdd(&g_ctr4[bg], 1u);
                volatile unsigned* vc = &g_ctr4[bg];
                while (*vc < target) { }
            }
            __syncthreads();
        }
        p ^= 1;
    }
}

// ---------------------------------------------------------------------------
// Fused head: out[m] = logsoftmax(f[m]) @ W_comb^T + b_comb
// ---------------------------------------------------------------------------
__global__ void __launch_bounds__(256)
k_final(const float* __restrict__ X, float* __restrict__ out) {
    __shared__ float Wc[NCLS * DD];
    __shared__ float ss[NCLS], bc[NCLS];
    int tid = threadIdx.x;
    for (int idx = tid; idx < NCLS * DD; idx += 256) Wc[idx] = g_Wc[idx];
    if (tid < NCLS) { ss[tid] = g_s[tid]; bc[tid] = g_bc[tid]; }
    __syncthreads();

    int w = tid >> 5, l = tid & 31;
    int m = (blockIdx.x << 3) + w;
    const float* xr = X + (size_t)m * DD;

    float f[16];
    #pragma unroll
    for (int i = 0; i < 16; i++) f[i] = xr[i * 32 + l];

    float mx = f[0];
    #pragma unroll
    for (int i = 1; i < 16; i++) mx = fmaxf(mx, f[i]);
    #pragma unroll
    for (int off = 16; off > 0; off >>= 1)
        mx = fmaxf(mx, __shfl_xor_sync(0xffffffffu, mx, off));

    float se = 0.0f;
    #pragma unroll
    for (int i = 0; i < 16; i++) se += __expf(f[i] - mx);
    #pragma unroll
    for (int off = 16; off > 0; off >>= 1)
        se += __shfl_xor_sync(0xffffffffu, se, off);
    float c = mx + __logf(se);

    #pragma unroll
    for (int n = 0; n < NCLS; n++) {
        float dot = 0.0f;
        const float* wr = Wc + n * DD;
        #pragma unroll
        for (int i = 0; i < 16; i++) dot += f[i] * wr[i * 32 + l];
        #pragma unroll
        for (int off = 16; off > 0; off >>= 1)
            dot += __shfl_xor_sync(0xffffffffu, dot, off);
        if (l == 0) out[m * NCLS + n] = dot - c * ss[n] + bc[n];
    }
}

// ---------------------------------------------------------------------------
// kernel_launch — ordered so k_scan is launch index 5 (ncu -s 5 -c 1 target)
// ---------------------------------------------------------------------------
extern "C" void kernel_launch(void* const* d_in, const int* in_sizes, int n_in,
                              void* d_out, int out_size) {
    (void)in_sizes; (void)out_size;
    if (n_in < 17) return;
    const float* x0     = (const float*)d_in[0];
    const float* W_ih   = (const float*)d_in[3];
    const float* W_hh   = (const float*)d_in[4];
    const float* b_ih   = (const float*)d_in[5];
    const float* b_hh   = (const float*)d_in[6];
    const float* W1     = (const float*)d_in[7];
    const float* bb1    = (const float*)d_in[8];
    const float* W2     = (const float*)d_in[9];
    const float* bb2    = (const float*)d_in[10];
    const float* W3     = (const float*)d_in[11];
    const float* bb3    = (const float*)d_in[12];
    const float* W_half = (const float*)d_in[13];
    const float* b_half = (const float*)d_in[14];
    const float* W_out  = (const float*)d_in[15];
    const float* b_out  = (const float*)d_in[16];
    float* out = (float*)d_out;

    float *gx, *x3;
    __nv_bfloat16 *A0, *e2, *x1b, *x2b, *Wih2, *W12, *W22, *W32;
    cudaGetSymbolAddress((void**)&gx,   g_gx);
    cudaGetSymbolAddress((void**)&x3,   g_x3);
    cudaGetSymbolAddress((void**)&A0,   g_A0);
    cudaGetSymbolAddress((void**)&e2,   g_e2);
    cudaGetSymbolAddress((void**)&x1b,  g_x1b);
    cudaGetSymbolAddress((void**)&x2b,  g_x2b);
    cudaGetSymbolAddress((void**)&Wih2, g_Wih2);
    cudaGetSymbolAddress((void**)&W12,  g_W12);
    cudaGetSymbolAddress((void**)&W22,  g_W22);
    cudaGetSymbolAddress((void**)&W32,  g_W32);

    cudaFuncSetAttribute(k_scan, cudaFuncAttributeMaxDynamicSharedMemorySize,
                         SCAN_SMEM_BYTES);
    cudaFuncSetAttribute(k_mma_gemm, cudaFuncAttributeMaxDynamicSharedMemorySize,
                         GEMM_SMEM);

    // 0,1: input/weight splits needed by gx GEMM
    k_split<<<(MROWS * 128) / 256, 256>>>(x0, A0, MROWS, 1);
    k_split<<<(1536 * 128) / 256, 256>>>(W_ih, Wih2, 1536, 0);
    // 2: init h planes + barrier counters
    k_init<<<256, 256>>>();
    // 3: gx = x0 @ W_ih^T + b_ih   [32768 x 1536]
    k_mma_gemm<<<256 * 12, 256, GEMM_SMEM>>>(A0, Wih2, b_ih, gx, 1536, 12, 0);
    // 4: head fold (independent)
    k_prep1<<<14, 256>>>(W_half, W_out);
    // 5: GRU scan (PROFILED)
    k_scan<<<128, 256, SCAN_SMEM_BYTES>>>(W_hh, b_hh);
    // 6: head fold part 2
    k_prep2<<<1, 256>>>(W_out, b_half, b_out);
    // 7-9: FFN weight splits
    k_split<<<(512 * 128) / 256, 256>>>(W1, W12, 512, 0);
    k_split<<<(512 * 128) / 256, 256>>>(W2, W22, 512, 0);
    k_split<<<(512 * 128) / 256, 256>>>(W3, W32, 512, 0);
    // 10-12: FFN
    k_mma_gemm<<<256 * 4, 256, GEMM_SMEM>>>(e2,  W12, bb1, x1b, 512, 4, 1);
    k_mma_gemm<<<256 * 4, 256, GEMM_SMEM>>>(x1b, W22, bb2, x2b, 512, 4, 1);
    k_mma_gemm<<<256 * 4, 256, GEMM_SMEM>>>(x2b, W32, bb3, x3,  512, 4, 0);
    // 13: fused log_softmax + combined classifier head
    k_final<<<MROWS / 8, 256>>>(x3, out);
}